// round 12
// baseline (speedup 1.0000x reference)
#include <cuda_runtime.h>
#include <math.h>
#include <stdint.h>

// Problem constants
#define BB     16
#define JJ     256
#define KK     384
#define CMETA  6
#define CIN    8
#define WD     32
#define DEPTH  3
#define SS     32
#define JK     (JJ*KK)        // 98304
#define NPTS   (BB*JK)        // 1572864

// tensor k_main config
#define MT_TPB   128          // 4 warps
#define MT_ROWS  128
#define MT_ITERS 4
#define MT_PTSBLK (MT_ROWS*MT_ITERS)   // 512
#define NMAINB  (NPTS/MT_PTSBLK)       // 3072

// front kernel: image blocks first, then compaction blocks
#define RPB   4
#define IMGB  (BB*(SS/RPB))      // 128 image blocks
#define ITB   192                // compute threads for image MLP (2 pts each)
#define CB    256
#define CPT   4
#define NCOMPB (NPTS/(CB*CPT))   // 1536

// dynamic smem layout for k_main
#define WF_U32    (3*4*2*2*32*4)   // 12288
#define WF0_U32   (2*2*32*4)       // 512
#define HROW_F32  (4*32*36)        // 4608
#define SMEM_BYTES ((WF_U32 + WF0_U32)*4 + (HROW_F32 + BB*WD + DEPTH*WD + WD + 4)*4 + 2*128*4 + 256)

// Scratch (device globals; zero at module load; k_main's last block re-zeros)
__device__ float g_img_sum[BB][WD];
__device__ float g_img_cnt[BB];
__device__ int   g_nact;
__device__ int   g_done;
__device__ int   g_idx[NPTS];

__device__ __forceinline__ bool mask_at(const void* m, int fmt, int i) {
    if (fmt == 0) return ((const unsigned char*)m)[i] != 0;
    if (fmt == 1) return ((const int*)m)[i] != 0;
    return ((const float*)m)[i] != 0.0f;
}

__device__ __forceinline__ int detect_fmt_block(const void* mask) {
    unsigned int v = ((const unsigned int*)mask)[threadIdx.x & 255];
    int all_int = __syncthreads_and(v <= 1u);
    int all_flt = __syncthreads_and(v == 0u || v == 0x3F800000u);
    return all_int ? 1 : (all_flt ? 2 : 0);
}

__device__ __forceinline__ unsigned int rotl32(unsigned int x, int r) {
    return (x << r) | (x >> (32 - r));
}

__device__ __forceinline__ uint32_t f2tf32(float f) {
    uint32_t u;
    asm("cvt.rna.tf32.f32 %0, %1;" : "=r"(u) : "f"(f));
    return u;
}
__device__ __forceinline__ void split_tf32(float v, uint32_t& hi, uint32_t& lo) {
    hi = f2tf32(v);
    lo = f2tf32(v - __uint_as_float(hi));
}
__device__ __forceinline__ void mma_tf32(float c[4],
                                         uint32_t a0, uint32_t a1, uint32_t a2, uint32_t a3,
                                         uint32_t b0, uint32_t b1) {
    asm("mma.sync.aligned.m16n8k8.row.col.f32.tf32.tf32.f32 "
        "{%0,%1,%2,%3},{%4,%5,%6,%7},{%8,%9},{%0,%1,%2,%3};"
        : "+f"(c[0]), "+f"(c[1]), "+f"(c[2]), "+f"(c[3])
        : "r"(a0), "r"(a1), "r"(a2), "r"(a3), "r"(b0), "r"(b1));
}

// ---------------------------------------------------------------------------
// Front kernel: blocks [0,IMGB) = image branch with LOCAL gumbel selection;
// blocks [IMGB,..) = stream compaction. Fully independent roles, one launch.
// ---------------------------------------------------------------------------
__global__ void __launch_bounds__(256) k_front(
    const void* __restrict__ mask,
    const float* __restrict__ Imodel, const float* __restrict__ Iobs,
    const float* __restrict__ metadata,
    const float* __restrict__ W_img_in, const float* __restrict__ b_img_in,
    const float* __restrict__ W_img, const float* __restrict__ b_img,
    float* __restrict__ out)
{
    const int fmt = detect_fmt_block(mask);
    const int tid = threadIdx.x;

    if (blockIdx.x >= IMGB) {
        // ---------------- compaction role ----------------
        const int cb = blockIdx.x - IMGB;
        const int lane = tid & 31;
        const int wid = tid >> 5;
        const unsigned int lt = (1u << lane) - 1u;
        const int base = cb * CB * CPT;

        bool act[CPT];
        unsigned int bal[CPT];
        int wcnt = 0;
#pragma unroll
        for (int r = 0; r < CPT; r++) {
            const int p = base + r * CB + tid;
            act[r] = mask_at(mask, fmt, p);
            bal[r] = __ballot_sync(0xFFFFFFFFu, act[r]);
            wcnt += __popc(bal[r]);
            if (!act[r]) out[p] = 0.0f;
        }

        __shared__ int wsum[8];
        __shared__ int bbase;
        if (lane == 0) wsum[wid] = wcnt;
        __syncthreads();
        if (tid == 0) {
            int tot = 0;
#pragma unroll
            for (int w = 0; w < 8; w++) { int c = wsum[w]; wsum[w] = tot; tot += c; }
            bbase = atomicAdd(&g_nact, tot);
        }
        __syncthreads();

        int off = bbase + wsum[wid];
#pragma unroll
        for (int r = 0; r < CPT; r++) {
            if (act[r]) g_idx[off + __popc(bal[r] & lt)] = base + r * CB + tid;
            off += __popc(bal[r]);
        }
        return;
    }

    // ---------------- image role (with local selection) ----------------
    const int b = blockIdx.x / (SS / RPB);
    const int s0 = (blockIdx.x % (SS / RPB)) * RPB;

    __shared__ unsigned int keys[JJ];
    __shared__ int selrows[RPB];
    __shared__ __align__(16) float W0s[WD * CIN];
    __shared__ __align__(16) float Ws[DEPTH * WD * WD];
    __shared__ float bs0[WD];
    __shared__ float bsd[DEPTH][WD];

    // --- local selection: row j = tid (all 256 threads) ---
    {
        const int j = tid;
        const int rbase = (b * JJ + j) * KK;
        bool alive = false;
        for (int k = 0; k < KK; k++) {
            if (mask_at(mask, fmt, rbase + k)) { alive = true; break; }
        }

        // JAX partitionable threefry2x32, key=(0,42); bits = out0 ^ out1
        const unsigned int n = (unsigned int)(b * JJ + j);
        unsigned int x0 = 0u;
        unsigned int x1 = n;
        const unsigned int ks0 = 0u;
        const unsigned int ks1 = 42u;
        const unsigned int ks2 = 0x1BD11BDAu ^ 42u;
        x0 += ks0; x1 += ks1;
#define TF_ROUND(r) { x0 += x1; x1 = rotl32(x1, (r)); x1 ^= x0; }
        TF_ROUND(13) TF_ROUND(15) TF_ROUND(26) TF_ROUND(6)
        x0 += ks1; x1 += ks2 + 1u;
        TF_ROUND(17) TF_ROUND(29) TF_ROUND(16) TF_ROUND(24)
        x0 += ks2; x1 += ks0 + 2u;
        TF_ROUND(13) TF_ROUND(15) TF_ROUND(26) TF_ROUND(6)
        x0 += ks0; x1 += ks1 + 3u;
        TF_ROUND(17) TF_ROUND(29) TF_ROUND(16) TF_ROUND(24)
        x0 += ks1; x1 += ks2 + 4u;
        TF_ROUND(13) TF_ROUND(15) TF_ROUND(26) TF_ROUND(6)
        x0 += ks2; x1 += ks0 + 5u;
#undef TF_ROUND
        const unsigned int bits = x0 ^ x1;
        const unsigned int keyv = alive ? ((bits >> 9) | 0x80000000u) : 0u;
        keys[j] = keyv;
        __syncthreads();

        int rank = 0;
        for (int t = 0; t < JJ; t++) {
            unsigned int s = keys[t];
            if (s > keyv || (s == keyv && t < j)) rank++;
        }
        if (rank >= s0 && rank < s0 + RPB) selrows[rank - s0] = j;
    }

    // --- stage weights (256 threads) ---
    for (int t = tid; t < CIN * WD; t += 256) {
        int i = t / WD, c = t % WD;
        W0s[c * CIN + i] = W_img_in[t];
    }
    for (int t = tid; t < DEPTH * WD * WD; t += 256) {
        int d = t / (WD * WD); int r = t % (WD * WD); int i = r / WD, c = r % WD;
        Ws[(d * WD + c) * WD + i] = W_img[t];
    }
    for (int t = tid; t < WD; t += 256) bs0[t] = b_img_in[t];
    for (int t = tid; t < DEPTH * WD; t += 256) bsd[t / WD][t % WD] = b_img[t];
    __syncthreads();

    if (tid >= ITB) return;    // 192 compute threads, 2 pts each per row

#pragma unroll 1
    for (int rr = 0; rr < RPB; rr++) {
        const int j = selrows[rr];
        const int base = (b * JJ + j) * KK;
        const int pA = base + tid;
        const int pB = base + tid + ITB;

        float x0[CIN], x1[CIN];
        x0[0] = Imodel[pA]; x1[0] = Imodel[pB];
        x0[1] = Iobs[pA];   x1[1] = Iobs[pB];
        {
            const float* m0 = metadata + (size_t)pA * CMETA;
            const float* m1 = metadata + (size_t)pB * CMETA;
#pragma unroll
            for (int i = 0; i < CMETA; i++) { x0[2 + i] = m0[i]; x1[2 + i] = m1[i]; }
        }

        float h0[WD], h1[WD], o0[WD], o1[WD];

#pragma unroll
        for (int c = 0; c < WD; c++) {
            float a0 = bs0[c], a1 = a0;
            const float4* wr = (const float4*)&W0s[c * CIN];
#pragma unroll
            for (int i4 = 0; i4 < 2; i4++) {
                float4 w = wr[i4];
                a0 = fmaf(x0[i4 * 4 + 0], w.x, a0);
                a0 = fmaf(x0[i4 * 4 + 1], w.y, a0);
                a0 = fmaf(x0[i4 * 4 + 2], w.z, a0);
                a0 = fmaf(x0[i4 * 4 + 3], w.w, a0);
                a1 = fmaf(x1[i4 * 4 + 0], w.x, a1);
                a1 = fmaf(x1[i4 * 4 + 1], w.y, a1);
                a1 = fmaf(x1[i4 * 4 + 2], w.z, a1);
                a1 = fmaf(x1[i4 * 4 + 3], w.w, a1);
            }
            h0[c] = a0; h1[c] = a1;
        }

#pragma unroll 1
        for (int d = 0; d < DEPTH; d++) {
            const float4* wl = (const float4*)&Ws[d * WD * WD];
#pragma unroll
            for (int c = 0; c < WD; c++) {
                float a0 = bsd[d][c], a1 = a0;
#pragma unroll
                for (int i4 = 0; i4 < 8; i4++) {
                    float4 w = wl[c * 8 + i4];
                    a0 = fmaf(h0[i4 * 4 + 0], w.x, a0);
                    a0 = fmaf(h0[i4 * 4 + 1], w.y, a0);
                    a0 = fmaf(h0[i4 * 4 + 2], w.z, a0);
                    a0 = fmaf(h0[i4 * 4 + 3], w.w, a0);
                    a1 = fmaf(h1[i4 * 4 + 0], w.x, a1);
                    a1 = fmaf(h1[i4 * 4 + 1], w.y, a1);
                    a1 = fmaf(h1[i4 * 4 + 2], w.z, a1);
                    a1 = fmaf(h1[i4 * 4 + 3], w.w, a1);
                }
                o0[c] = fmaxf(a0, 0.0f);
                o1[c] = fmaxf(a1, 0.0f);
            }
#pragma unroll
            for (int c = 0; c < WD; c++) { h0[c] = o0[c]; h1[c] = o1[c]; }
        }

        const float m0 = mask_at(mask, fmt, pA) ? 1.0f : 0.0f;
        const float m1 = mask_at(mask, fmt, pB) ? 1.0f : 0.0f;

#pragma unroll
        for (int c = 0; c < WD; c++) {
            float v = m0 * h0[c] + m1 * h1[c];
#pragma unroll
            for (int o = 16; o > 0; o >>= 1) v += __shfl_xor_sync(0xFFFFFFFFu, v, o);
            if ((tid & 31) == 0) atomicAdd(&g_img_sum[b][c], v);
        }
        {
            float v = m0 + m1;
#pragma unroll
            for (int o = 16; o > 0; o >>= 1) v += __shfl_xor_sync(0xFFFFFFFFu, v, o);
            if ((tid & 31) == 0) atomicAdd(&g_img_cnt[b], v);
        }
    }
}

// ---------------------------------------------------------------------------
// Kernel 2: main branch on tensor cores (tf32 mma, 3-pass hi/lo split).
// Last-finishing block resets ALL replay state (g_nact, g_img_sum, g_img_cnt).
// ---------------------------------------------------------------------------
__global__ void __launch_bounds__(MT_TPB, 3) k_main(
    const float* __restrict__ metadata,
    const float* __restrict__ W_lin_in, const float* __restrict__ b_lin_in,
    const float* __restrict__ W_mlp, const float* __restrict__ b_mlp,
    const float* __restrict__ W_out, const float* __restrict__ b_out,
    float* __restrict__ out)
{
    extern __shared__ __align__(16) unsigned char dynsmem[];
    uint32_t* Wf   = (uint32_t*)dynsmem;
    uint32_t* Wf0  = Wf + WF_U32;
    float* hrow    = (float*)(Wf0 + WF0_U32);
    float* beffs   = hrow + HROW_F32;
    float* bsd     = beffs + BB * WD;
    float* wout_s  = bsd + DEPTH * WD;
    float* bout_s  = wout_s + WD;
    int*   xb      = (int*)(bout_s + 4);
    int*   xp      = xb + 128;

    const int tid = threadIdx.x;

    for (int t = tid; t < 3 * 4 * 2 * 32 * 4; t += MT_TPB) {
        int nt = t & 3, lane = (t >> 2) & 31, reg = (t >> 7) & 1;
        int kt = (t >> 8) & 3, d = t >> 10;
        int k = (lane & 3) + 4 * reg + 8 * kt;
        int nn = (lane >> 2) + 8 * nt;
        float w = W_mlp[(d * WD + k) * WD + nn];
        uint32_t hi, lo; split_tf32(w, hi, lo);
        int basei = (((d * 4 + kt) * 2 + reg) * 2) * 128 + lane * 4 + nt;
        Wf[basei] = hi;
        Wf[basei + 128] = lo;
    }
    for (int t = tid; t < 2 * 32 * 4; t += MT_TPB) {
        int nt = t & 3, lane = (t >> 2) & 31, reg = t >> 7;
        int k = (lane & 3) + 4 * reg;
        int nn = (lane >> 2) + 8 * nt;
        float w = (k < CMETA) ? W_lin_in[k * WD + nn] : 0.0f;
        uint32_t hi, lo; split_tf32(w, hi, lo);
        Wf0[(reg * 2) * 128 + lane * 4 + nt] = hi;
        Wf0[(reg * 2 + 1) * 128 + lane * 4 + nt] = lo;
    }
    for (int t = tid; t < BB * WD; t += MT_TPB) {
        int bb = t / WD, c = t % WD;
        beffs[t] = b_lin_in[c] + g_img_sum[bb][c] / g_img_cnt[bb];
    }
    for (int t = tid; t < DEPTH * WD; t += MT_TPB) bsd[t] = b_mlp[t];
    if (tid < WD) wout_s[tid] = W_out[tid];
    if (tid == 0) bout_s[0] = b_out[0];
    __syncthreads();

    const int n_act = g_nact;
    const int w = tid >> 5;
    const int lane = tid & 31;
    const int g = lane >> 2;
    const int q = lane & 3;
    const int blkbase = blockIdx.x * MT_PTSBLK;

    float wo[8];
#pragma unroll
    for (int nt = 0; nt < 4; nt++) {
        wo[nt * 2 + 0] = wout_s[8 * nt + 2 * q + 0];
        wo[nt * 2 + 1] = wout_s[8 * nt + 2 * q + 1];
    }
    const float boutv = bout_s[0];
    float* myrows = hrow + w * 32 * 36;
    int* myxb = xb + w * 32;
    int* myxp = xp + w * 32;

    if (blkbase < n_act) {
#pragma unroll 1
        for (int it = 0; it < MT_ITERS; it++) {
            if (blkbase + it * MT_ROWS >= n_act) break;
            const int slot = blkbase + it * MT_ROWS + tid;
            const bool valid = slot < n_act;
            const int p = valid ? g_idx[slot] : 0;

            __syncwarp();
            {
                const float* mp = metadata + (size_t)p * CMETA;
                float* xr = myrows + lane * 36;
#pragma unroll
                for (int i = 0; i < CMETA; i++) xr[i] = mp[i];
                xr[6] = 0.0f; xr[7] = 0.0f;
                myxb[lane] = p / JK;
                myxp[lane] = valid ? p : -1;
            }
            __syncwarp();

            const int b4[4] = { myxb[g], myxb[g + 8], myxb[g + 16], myxb[g + 24] };

            float cc[2][4][4];
#pragma unroll
            for (int mt = 0; mt < 2; mt++)
#pragma unroll
                for (int nt = 0; nt < 4; nt++)
#pragma unroll
                    for (int r = 0; r < 4; r++) cc[mt][nt][r] = 0.0f;

            {
                uint32_t ah[2][4], al[2][4];
#pragma unroll
                for (int mt = 0; mt < 2; mt++) {
                    const int R = 16 * mt;
                    split_tf32(myrows[(R + g) * 36 + q],          ah[mt][0], al[mt][0]);
                    split_tf32(myrows[(R + g + 8) * 36 + q],      ah[mt][1], al[mt][1]);
                    split_tf32(myrows[(R + g) * 36 + q + 4],      ah[mt][2], al[mt][2]);
                    split_tf32(myrows[(R + g + 8) * 36 + q + 4],  ah[mt][3], al[mt][3]);
                }
                uint4 b0h = *(const uint4*)&Wf0[0 * 128 + lane * 4];
                uint4 b0l = *(const uint4*)&Wf0[1 * 128 + lane * 4];
                uint4 b1h = *(const uint4*)&Wf0[2 * 128 + lane * 4];
                uint4 b1l = *(const uint4*)&Wf0[3 * 128 + lane * 4];
                uint32_t B0H[4] = {b0h.x, b0h.y, b0h.z, b0h.w};
                uint32_t B0L[4] = {b0l.x, b0l.y, b0l.z, b0l.w};
                uint32_t B1H[4] = {b1h.x, b1h.y, b1h.z, b1h.w};
                uint32_t B1L[4] = {b1l.x, b1l.y, b1l.z, b1l.w};
#pragma unroll
                for (int mt = 0; mt < 2; mt++)
#pragma unroll
                    for (int nt = 0; nt < 4; nt++) {
                        mma_tf32(cc[mt][nt], ah[mt][0], ah[mt][1], ah[mt][2], ah[mt][3], B0H[nt], B1H[nt]);
                        mma_tf32(cc[mt][nt], al[mt][0], al[mt][1], al[mt][2], al[mt][3], B0H[nt], B1H[nt]);
                        mma_tf32(cc[mt][nt], ah[mt][0], ah[mt][1], ah[mt][2], ah[mt][3], B0L[nt], B1L[nt]);
                    }
            }

            __syncwarp();
#pragma unroll
            for (int mt = 0; mt < 2; mt++)
#pragma unroll
                for (int nt = 0; nt < 4; nt++)
#pragma unroll
                    for (int r = 0; r < 4; r++) {
                        int rowl = 16 * mt + g + 8 * (r >> 1);
                        int col = 8 * nt + 2 * q + (r & 1);
                        int bi = b4[mt * 2 + (r >> 1)];
                        myrows[rowl * 36 + col] = cc[mt][nt][r] + beffs[bi * WD + col];
                    }
            __syncwarp();

            float acc[4] = {0.0f, 0.0f, 0.0f, 0.0f};
#pragma unroll
            for (int d = 0; d < DEPTH; d++) {
#pragma unroll
                for (int mt = 0; mt < 2; mt++)
#pragma unroll
                    for (int nt = 0; nt < 4; nt++)
#pragma unroll
                        for (int r = 0; r < 4; r++) cc[mt][nt][r] = 0.0f;

#pragma unroll
                for (int kt = 0; kt < 4; kt++) {
                    uint32_t ah[2][4], al[2][4];
                    const int kc = 8 * kt;
#pragma unroll
                    for (int mt = 0; mt < 2; mt++) {
                        const int R = 16 * mt;
                        split_tf32(myrows[(R + g) * 36 + kc + q],         ah[mt][0], al[mt][0]);
                        split_tf32(myrows[(R + g + 8) * 36 + kc + q],     ah[mt][1], al[mt][1]);
                        split_tf32(myrows[(R + g) * 36 + kc + q + 4],     ah[mt][2], al[mt][2]);
                        split_tf32(myrows[(R + g + 8) * 36 + kc + q + 4], ah[mt][3], al[mt][3]);
                    }
                    const int wbase = ((d * 4 + kt) * 4) * 128 + lane * 4;
                    uint4 b0h = *(const uint4*)&Wf[wbase];
                    uint4 b0l = *(const uint4*)&Wf[wbase + 128];
                    uint4 b1h = *(const uint4*)&Wf[wbase + 256];
                    uint4 b1l = *(const uint4*)&Wf[wbase + 384];
                    uint32_t B0H[4] = {b0h.x, b0h.y, b0h.z, b0h.w};
                    uint32_t B0L[4] = {b0l.x, b0l.y, b0l.z, b0l.w};
                    uint32_t B1H[4] = {b1h.x, b1h.y, b1h.z, b1h.w};
                    uint32_t B1L[4] = {b1l.x, b1l.y, b1l.z, b1l.w};
#pragma unroll
                    for (int mt = 0; mt < 2; mt++)
#pragma unroll
                        for (int nt = 0; nt < 4; nt++) {
                            mma_tf32(cc[mt][nt], ah[mt][0], ah[mt][1], ah[mt][2], ah[mt][3], B0H[nt], B1H[nt]);
                            mma_tf32(cc[mt][nt], al[mt][0], al[mt][1], al[mt][2], al[mt][3], B0H[nt], B1H[nt]);
                            mma_tf32(cc[mt][nt], ah[mt][0], ah[mt][1], ah[mt][2], ah[mt][3], B0L[nt], B1L[nt]);
                        }
                }

                __syncwarp();
#pragma unroll
                for (int mt = 0; mt < 2; mt++)
#pragma unroll
                    for (int nt = 0; nt < 4; nt++)
#pragma unroll
                        for (int r = 0; r < 4; r++) {
                            int col = 8 * nt + 2 * q + (r & 1);
                            float hv = fmaxf(cc[mt][nt][r] + bsd[d * WD + col], 0.0f);
                            if (d < DEPTH - 1) {
                                int rowl = 16 * mt + g + 8 * (r >> 1);
                                myrows[rowl * 36 + col] = hv;
                            } else {
                                acc[mt * 2 + (r >> 1)] = fmaf(hv, wo[nt * 2 + (r & 1)], acc[mt * 2 + (r >> 1)]);
                            }
                        }
                __syncwarp();
            }

#pragma unroll
            for (int jj = 0; jj < 4; jj++) {
                acc[jj] += __shfl_xor_sync(0xFFFFFFFFu, acc[jj], 1);
                acc[jj] += __shfl_xor_sync(0xFFFFFFFFu, acc[jj], 2);
            }
            if (q == 0) {
#pragma unroll
                for (int jj = 0; jj < 4; jj++) {
                    int rowl = 16 * (jj >> 1) + g + 8 * (jj & 1);
                    int pt = myxp[rowl];
                    if (pt >= 0) out[pt] = acc[jj] + boutv;
                }
            }
        }
    }

    // replay-state reset: last block out resets everything
    __syncthreads();
    if (tid == 0) {
        int old = atomicAdd(&g_done, 1);
        if (old == (int)gridDim.x - 1) {
            g_nact = 0;
            float* s = &g_img_sum[0][0];
            for (int t = 0; t < BB * WD; t++) s[t] = 0.0f;
            for (int t = 0; t < BB; t++) g_img_cnt[t] = 0.0f;
            __threadfence();
            g_done = 0;
        }
    }
}

// ---------------------------------------------------------------------------
extern "C" void kernel_launch(void* const* d_in, const int* in_sizes, int n_in,
                              void* d_out, int out_size)
{
    const float* Imodel   = (const float*)d_in[0];
    const float* Iobs     = (const float*)d_in[1];
    const float* metadata = (const float*)d_in[2];
    const void*  mask     = d_in[3];
    const float* W_img_in = (const float*)d_in[5];
    const float* b_img_in = (const float*)d_in[6];
    const float* W_img    = (const float*)d_in[7];
    const float* b_img    = (const float*)d_in[8];
    const float* W_lin_in = (const float*)d_in[9];
    const float* b_lin_in = (const float*)d_in[10];
    const float* W_mlp    = (const float*)d_in[11];
    const float* b_mlp    = (const float*)d_in[12];
    const float* W_out    = (const float*)d_in[13];
    const float* b_out    = (const float*)d_in[14];
    float* out = (float*)d_out;

    static int smem_set = 0;
    if (!smem_set) {
        cudaFuncSetAttribute(k_main, cudaFuncAttributeMaxDynamicSharedMemorySize,
                             SMEM_BYTES);
        smem_set = 1;
    }

    k_front<<<IMGB + NCOMPB, 256>>>(mask, Imodel, Iobs, metadata,
                                    W_img_in, b_img_in, W_img, b_img, out);
    k_main<<<NMAINB, MT_TPB, SMEM_BYTES>>>(metadata, W_lin_in, b_lin_in,
                                           W_mlp, b_mlp, W_out, b_out, out);
}

// round 13
// speedup vs baseline: 1.0316x; 1.0316x over previous
#include <cuda_runtime.h>
#include <cuda_fp16.h>
#include <math.h>
#include <stdint.h>
#include <string.h>

// Problem constants
#define BB     16
#define JJ     256
#define KK     384
#define CMETA  6
#define CIN    8
#define WD     32
#define DEPTH  3
#define SS     32
#define JK     (JJ*KK)        // 98304
#define NPTS   (BB*JK)        // 1572864

// tensor k_main config
#define MT_TPB   128          // 4 warps
#define MT_ROWS  128
#define MT_ITERS 4
#define MT_PTSBLK (MT_ROWS*MT_ITERS)   // 512
#define NMAINB  (NPTS/MT_PTSBLK)       // 3072

// front kernel: image blocks first, then compaction blocks
#define RPB   1
#define IMGB  (BB*SS)            // 512 image blocks (1 row each)
#define ITB   192                // compute threads for image MLP (2 pts each)
#define CB    256
#define CPT   4
#define NCOMPB (NPTS/(CB*CPT))   // 1536

// k_main dynamic SMEM layout
#define WF4_N   (3*2*32*4)       // 768 uint4 (hidden-layer B frags)
#define WF0_N   (32*4)           // 128 uint2 (input-layer B frags)
#define HSTRIDE 20               // uint32 stride per row (16 pairs + pad)
#define HROW_N  (4*32*HSTRIDE)   // per hi/lo array
#define SMEM_BYTES (WF4_N*16 + WF0_N*8 + 2*HROW_N*4 + (BB*WD + DEPTH*WD + WD + 4)*4 + 2*128*4 + 256)

// Scratch (device globals; zero at module load; k_main's last block re-zeros)
__device__ float g_img_sum[BB][WD];
__device__ float g_img_cnt[BB];
__device__ int   g_nact;
__device__ int   g_done;
__device__ int   g_idx[NPTS];

__device__ __forceinline__ bool mask_at(const void* m, int fmt, int i) {
    if (fmt == 0) return ((const unsigned char*)m)[i] != 0;
    if (fmt == 1) return ((const int*)m)[i] != 0;
    return ((const float*)m)[i] != 0.0f;
}

__device__ __forceinline__ int detect_fmt_block(const void* mask) {
    unsigned int v = ((const unsigned int*)mask)[threadIdx.x & 255];
    int all_int = __syncthreads_and(v <= 1u);
    int all_flt = __syncthreads_and(v == 0u || v == 0x3F800000u);
    return all_int ? 1 : (all_flt ? 2 : 0);
}

__device__ __forceinline__ unsigned int rotl32(unsigned int x, int r) {
    return (x << r) | (x >> (32 - r));
}

// ---- fp16 split helpers ----
__device__ __forceinline__ uint32_t h2u(__half2 h) {
    uint32_t u; memcpy(&u, &h, 4); return u;
}
// pack (v_even -> low, v_odd -> high) split into hi2/lo2 half2 regs
__device__ __forceinline__ void split_h2(float v0, float v1,
                                         uint32_t& hi2, uint32_t& lo2) {
    __half2 h = __floats2half2_rn(v0, v1);          // low=v0, high=v1
    float e0 = __low2float(h);
    float e1 = __high2float(h);
    __half2 l = __floats2half2_rn(v0 - e0, v1 - e1);
    hi2 = h2u(h); lo2 = h2u(l);
}
__device__ __forceinline__ void mma_f16(float c[4],
                                        uint32_t a0, uint32_t a1, uint32_t a2, uint32_t a3,
                                        uint32_t b0, uint32_t b1) {
    asm("mma.sync.aligned.m16n8k16.row.col.f32.f16.f16.f32 "
        "{%0,%1,%2,%3},{%4,%5,%6,%7},{%8,%9},{%0,%1,%2,%3};"
        : "+f"(c[0]), "+f"(c[1]), "+f"(c[2]), "+f"(c[3])
        : "r"(a0), "r"(a1), "r"(a2), "r"(a3), "r"(b0), "r"(b1));
}

// ---------------------------------------------------------------------------
// Front kernel: blocks [0,IMGB) = image branch with LOCAL gumbel selection
// (1 sampled row per block); blocks [IMGB,..) = stream compaction.
// ---------------------------------------------------------------------------
__global__ void __launch_bounds__(256) k_front(
    const void* __restrict__ mask,
    const float* __restrict__ Imodel, const float* __restrict__ Iobs,
    const float* __restrict__ metadata,
    const float* __restrict__ W_img_in, const float* __restrict__ b_img_in,
    const float* __restrict__ W_img, const float* __restrict__ b_img,
    float* __restrict__ out)
{
    const int fmt = detect_fmt_block(mask);
    const int tid = threadIdx.x;

    if (blockIdx.x >= IMGB) {
        // ---------------- compaction role ----------------
        const int cb = blockIdx.x - IMGB;
        const int lane = tid & 31;
        const int wid = tid >> 5;
        const unsigned int lt = (1u << lane) - 1u;
        const int base = cb * CB * CPT;

        bool act[CPT];
        unsigned int bal[CPT];
        int wcnt = 0;
#pragma unroll
        for (int r = 0; r < CPT; r++) {
            const int p = base + r * CB + tid;
            act[r] = mask_at(mask, fmt, p);
            bal[r] = __ballot_sync(0xFFFFFFFFu, act[r]);
            wcnt += __popc(bal[r]);
            if (!act[r]) out[p] = 0.0f;
        }

        __shared__ int wsum[8];
        __shared__ int bbase;
        if (lane == 0) wsum[wid] = wcnt;
        __syncthreads();
        if (tid == 0) {
            int tot = 0;
#pragma unroll
            for (int w = 0; w < 8; w++) { int c = wsum[w]; wsum[w] = tot; tot += c; }
            bbase = atomicAdd(&g_nact, tot);
        }
        __syncthreads();

        int off = bbase + wsum[wid];
#pragma unroll
        for (int r = 0; r < CPT; r++) {
            if (act[r]) g_idx[off + __popc(bal[r] & lt)] = base + r * CB + tid;
            off += __popc(bal[r]);
        }
        return;
    }

    // ---------------- image role (local selection, 1 row) ----------------
    const int b = blockIdx.x / SS;
    const int s0 = blockIdx.x % SS;

    __shared__ unsigned int keys[JJ];
    __shared__ int selrow;
    __shared__ __align__(16) float W0s[WD * CIN];
    __shared__ __align__(16) float Ws[DEPTH * WD * WD];
    __shared__ float bs0[WD];
    __shared__ float bsd[DEPTH][WD];

    {
        const int j = tid;
        const int rbase = (b * JJ + j) * KK;
        bool alive = false;
        for (int k = 0; k < KK; k++) {
            if (mask_at(mask, fmt, rbase + k)) { alive = true; break; }
        }

        const unsigned int n = (unsigned int)(b * JJ + j);
        unsigned int x0 = 0u;
        unsigned int x1 = n;
        const unsigned int ks0 = 0u;
        const unsigned int ks1 = 42u;
        const unsigned int ks2 = 0x1BD11BDAu ^ 42u;
        x0 += ks0; x1 += ks1;
#define TF_ROUND(r) { x0 += x1; x1 = rotl32(x1, (r)); x1 ^= x0; }
        TF_ROUND(13) TF_ROUND(15) TF_ROUND(26) TF_ROUND(6)
        x0 += ks1; x1 += ks2 + 1u;
        TF_ROUND(17) TF_ROUND(29) TF_ROUND(16) TF_ROUND(24)
        x0 += ks2; x1 += ks0 + 2u;
        TF_ROUND(13) TF_ROUND(15) TF_ROUND(26) TF_ROUND(6)
        x0 += ks0; x1 += ks1 + 3u;
        TF_ROUND(17) TF_ROUND(29) TF_ROUND(16) TF_ROUND(24)
        x0 += ks1; x1 += ks2 + 4u;
        TF_ROUND(13) TF_ROUND(15) TF_ROUND(26) TF_ROUND(6)
        x0 += ks2; x1 += ks0 + 5u;
#undef TF_ROUND
        const unsigned int bits = x0 ^ x1;
        const unsigned int keyv = alive ? ((bits >> 9) | 0x80000000u) : 0u;
        keys[j] = keyv;
        __syncthreads();

        int rank = 0;
        for (int t = 0; t < JJ; t++) {
            unsigned int s = keys[t];
            if (s > keyv || (s == keyv && t < j)) rank++;
        }
        if (rank == s0) selrow = j;
    }

    for (int t = tid; t < CIN * WD; t += 256) {
        int i = t / WD, c = t % WD;
        W0s[c * CIN + i] = W_img_in[t];
    }
    for (int t = tid; t < DEPTH * WD * WD; t += 256) {
        int d = t / (WD * WD); int r = t % (WD * WD); int i = r / WD, c = r % WD;
        Ws[(d * WD + c) * WD + i] = W_img[t];
    }
    for (int t = tid; t < WD; t += 256) bs0[t] = b_img_in[t];
    for (int t = tid; t < DEPTH * WD; t += 256) bsd[t / WD][t % WD] = b_img[t];
    __syncthreads();

    if (tid >= ITB) return;

    const int j = selrow;
    const int base = (b * JJ + j) * KK;
    const int pA = base + tid;
    const int pB = base + tid + ITB;

    float x0[CIN], x1[CIN];
    x0[0] = Imodel[pA]; x1[0] = Imodel[pB];
    x0[1] = Iobs[pA];   x1[1] = Iobs[pB];
    {
        const float* m0 = metadata + (size_t)pA * CMETA;
        const float* m1 = metadata + (size_t)pB * CMETA;
#pragma unroll
        for (int i = 0; i < CMETA; i++) { x0[2 + i] = m0[i]; x1[2 + i] = m1[i]; }
    }

    float h0[WD], h1[WD], o0[WD], o1[WD];

#pragma unroll
    for (int c = 0; c < WD; c++) {
        float a0 = bs0[c], a1 = a0;
        const float4* wr = (const float4*)&W0s[c * CIN];
#pragma unroll
        for (int i4 = 0; i4 < 2; i4++) {
            float4 w = wr[i4];
            a0 = fmaf(x0[i4 * 4 + 0], w.x, a0);
            a0 = fmaf(x0[i4 * 4 + 1], w.y, a0);
            a0 = fmaf(x0[i4 * 4 + 2], w.z, a0);
            a0 = fmaf(x0[i4 * 4 + 3], w.w, a0);
            a1 = fmaf(x1[i4 * 4 + 0], w.x, a1);
            a1 = fmaf(x1[i4 * 4 + 1], w.y, a1);
            a1 = fmaf(x1[i4 * 4 + 2], w.z, a1);
            a1 = fmaf(x1[i4 * 4 + 3], w.w, a1);
        }
        h0[c] = a0; h1[c] = a1;
    }

#pragma unroll 1
    for (int d = 0; d < DEPTH; d++) {
        const float4* wl = (const float4*)&Ws[d * WD * WD];
#pragma unroll
        for (int c = 0; c < WD; c++) {
            float a0 = bsd[d][c], a1 = a0;
#pragma unroll
            for (int i4 = 0; i4 < 8; i4++) {
                float4 w = wl[c * 8 + i4];
                a0 = fmaf(h0[i4 * 4 + 0], w.x, a0);
                a0 = fmaf(h0[i4 * 4 + 1], w.y, a0);
                a0 = fmaf(h0[i4 * 4 + 2], w.z, a0);
                a0 = fmaf(h0[i4 * 4 + 3], w.w, a0);
                a1 = fmaf(h1[i4 * 4 + 0], w.x, a1);
                a1 = fmaf(h1[i4 * 4 + 1], w.y, a1);
                a1 = fmaf(h1[i4 * 4 + 2], w.z, a1);
                a1 = fmaf(h1[i4 * 4 + 3], w.w, a1);
            }
            o0[c] = fmaxf(a0, 0.0f);
            o1[c] = fmaxf(a1, 0.0f);
        }
#pragma unroll
        for (int c = 0; c < WD; c++) { h0[c] = o0[c]; h1[c] = o1[c]; }
    }

    const float m0 = mask_at(mask, fmt, pA) ? 1.0f : 0.0f;
    const float m1 = mask_at(mask, fmt, pB) ? 1.0f : 0.0f;

#pragma unroll
    for (int c = 0; c < WD; c++) {
        float v = m0 * h0[c] + m1 * h1[c];
#pragma unroll
        for (int o = 16; o > 0; o >>= 1) v += __shfl_xor_sync(0xFFFFFFFFu, v, o);
        if ((tid & 31) == 0) atomicAdd(&g_img_sum[b][c], v);
    }
    {
        float v = m0 + m1;
#pragma unroll
        for (int o = 16; o > 0; o >>= 1) v += __shfl_xor_sync(0xFFFFFFFFu, v, o);
        if ((tid & 31) == 0) atomicAdd(&g_img_cnt[b], v);
    }
}

// ---------------------------------------------------------------------------
// Kernel 2: main branch on tensor cores — fp16 m16n8k16 with Markidis 3-pass
// hi/lo split. Activations live in SMEM pre-split as half2 (hi,lo) arrays.
// ---------------------------------------------------------------------------
__global__ void __launch_bounds__(MT_TPB, 4) k_main(
    const float* __restrict__ metadata,
    const float* __restrict__ W_lin_in, const float* __restrict__ b_lin_in,
    const float* __restrict__ W_mlp, const float* __restrict__ b_mlp,
    const float* __restrict__ W_out, const float* __restrict__ b_out,
    float* __restrict__ out)
{
    extern __shared__ __align__(16) unsigned char dynsmem[];
    uint4* WF4   = (uint4*)dynsmem;                 // [d][kt][lane][nt] = (b0h,b1h,b0l,b1l)
    uint2* WF0   = (uint2*)(WF4 + WF4_N);           // [lane][nt] = (b0h,b0l)
    uint32_t* HH = (uint32_t*)(WF0 + WF0_N);        // [warp][row][HSTRIDE] hi pairs
    uint32_t* HL = HH + HROW_N;                     // lo pairs
    float* beffs = (float*)(HL + HROW_N);           // [16][32]
    float* bsd   = beffs + BB * WD;                 // [3][32]
    float* wout_s= bsd + DEPTH * WD;                // [32]
    float* bout_s= wout_s + WD;                     // [1]
    int*   xb    = (int*)(bout_s + 4);              // [4][32]
    int*   xp    = xb + 128;                        // [4][32]

    const int tid = threadIdx.x;

    // ---- stage hidden-layer weight fragments (fp16 hi/lo) ----
    for (int t = tid; t < 3 * 2 * 32 * 4; t += MT_TPB) {   // 768
        int nt = t & 3, lane = (t >> 2) & 31, kt = (t >> 7) & 1, d = t >> 8;
        int n = (lane >> 2) + 8 * nt;
        int k0 = 2 * (lane & 3) + 16 * kt;
        uint32_t b0h, b0l, b1h, b1l;
        split_h2(W_mlp[(d * WD + k0) * WD + n],     W_mlp[(d * WD + k0 + 1) * WD + n], b0h, b0l);
        split_h2(W_mlp[(d * WD + k0 + 8) * WD + n], W_mlp[(d * WD + k0 + 9) * WD + n], b1h, b1l);
        WF4[((d * 2 + kt) * 32 + lane) * 4 + nt] = make_uint4(b0h, b1h, b0l, b1l);
    }
    // ---- input-layer weight fragments (k<8 only; b1 tile is all-zero) ----
    for (int t = tid; t < 32 * 4; t += MT_TPB) {
        int nt = t & 3, lane = t >> 2;
        int n = (lane >> 2) + 8 * nt;
        int k0 = 2 * (lane & 3);
        float w0 = (k0 < CMETA) ? W_lin_in[k0 * WD + n] : 0.0f;
        float w1 = (k0 + 1 < CMETA) ? W_lin_in[(k0 + 1) * WD + n] : 0.0f;
        uint32_t bh, bl;
        split_h2(w0, w1, bh, bl);
        WF0[lane * 4 + nt] = make_uint2(bh, bl);
    }
    for (int t = tid; t < BB * WD; t += MT_TPB) {
        int bb = t / WD, c = t % WD;
        beffs[t] = b_lin_in[c] + g_img_sum[bb][c] / g_img_cnt[bb];
    }
    for (int t = tid; t < DEPTH * WD; t += MT_TPB) bsd[t] = b_mlp[t];
    if (tid < WD) wout_s[tid] = W_out[tid];
    if (tid == 0) bout_s[0] = b_out[0];
    __syncthreads();

    const int n_act = g_nact;
    const int w = tid >> 5;
    const int lane = tid & 31;
    const int g = lane >> 2;
    const int q = lane & 3;
    const int blkbase = blockIdx.x * MT_PTSBLK;

    float wo[8];
#pragma unroll
    for (int nt = 0; nt < 4; nt++) {
        wo[nt * 2 + 0] = wout_s[8 * nt + 2 * q + 0];
        wo[nt * 2 + 1] = wout_s[8 * nt + 2 * q + 1];
    }
    const float boutv = bout_s[0];
    uint32_t* mHH = HH + w * 32 * HSTRIDE;
    uint32_t* mHL = HL + w * 32 * HSTRIDE;
    int* myxb = xb + w * 32;
    int* myxp = xp + w * 32;

    if (blkbase < n_act) {
#pragma unroll 1
        for (int it = 0; it < MT_ITERS; it++) {
            if (blkbase + it * MT_ROWS >= n_act) break;
            const int slot = blkbase + it * MT_ROWS + tid;
            const bool valid = slot < n_act;
            const int p = valid ? g_idx[slot] : 0;

            __syncwarp();
            // stage this thread's input row as split half2 pairs (pairs 0..3)
            {
                const float* mp = metadata + (size_t)p * CMETA;
                float xv[8];
#pragma unroll
                for (int i = 0; i < CMETA; i++) xv[i] = mp[i];
                xv[6] = 0.0f; xv[7] = 0.0f;
                uint32_t* hr = mHH + lane * HSTRIDE;
                uint32_t* lr = mHL + lane * HSTRIDE;
#pragma unroll
                for (int pr = 0; pr < 4; pr++) {
                    uint32_t hi2, lo2;
                    split_h2(xv[2 * pr], xv[2 * pr + 1], hi2, lo2);
                    hr[pr] = hi2; lr[pr] = lo2;
                }
                myxb[lane] = p / JK;
                myxp[lane] = valid ? p : -1;
            }
            __syncwarp();

            const int b4[4] = { myxb[g], myxb[g + 8], myxb[g + 16], myxb[g + 24] };

            float cc[2][4][4];
#pragma unroll
            for (int mt = 0; mt < 2; mt++)
#pragma unroll
                for (int nt = 0; nt < 4; nt++)
#pragma unroll
                    for (int r = 0; r < 4; r++) cc[mt][nt][r] = 0.0f;

            // ---- input layer: single k16 tile, upper half zero ----
            {
                uint32_t aH[2][2], aL[2][2];
#pragma unroll
                for (int mt = 0; mt < 2; mt++) {
                    const int R = 16 * mt;
                    aH[mt][0] = mHH[(R + g) * HSTRIDE + q];
                    aH[mt][1] = mHH[(R + g + 8) * HSTRIDE + q];
                    aL[mt][0] = mHL[(R + g) * HSTRIDE + q];
                    aL[mt][1] = mHL[(R + g + 8) * HSTRIDE + q];
                }
#pragma unroll
                for (int nt = 0; nt < 4; nt++) {
                    uint2 wv = WF0[lane * 4 + nt];
#pragma unroll
                    for (int mt = 0; mt < 2; mt++) {
                        mma_f16(cc[mt][nt], aH[mt][0], aH[mt][1], 0u, 0u, wv.x, 0u);
                        mma_f16(cc[mt][nt], aL[mt][0], aL[mt][1], 0u, 0u, wv.x, 0u);
                        mma_f16(cc[mt][nt], aH[mt][0], aH[mt][1], 0u, 0u, wv.y, 0u);
                    }
                }
            }

            // input epilogue: + per-batch folded bias, split-store
            __syncwarp();
#pragma unroll
            for (int mt = 0; mt < 2; mt++)
#pragma unroll
                for (int nt = 0; nt < 4; nt++)
#pragma unroll
                    for (int rh = 0; rh < 2; rh++) {
                        int rowl = 16 * mt + g + 8 * rh;
                        int c0 = 8 * nt + 2 * q;
                        int bi = b4[mt * 2 + rh];
                        float v0 = cc[mt][nt][2 * rh]     + beffs[bi * WD + c0];
                        float v1 = cc[mt][nt][2 * rh + 1] + beffs[bi * WD + c0 + 1];
                        uint32_t hi2, lo2;
                        split_h2(v0, v1, hi2, lo2);
                        mHH[rowl * HSTRIDE + 4 * nt + q] = hi2;
                        mHL[rowl * HSTRIDE + 4 * nt + q] = lo2;
                    }
            __syncwarp();

            // ---- hidden layers ----
            float acc[4] = {0.0f, 0.0f, 0.0f, 0.0f};
#pragma unroll
            for (int d = 0; d < DEPTH; d++) {
#pragma unroll
                for (int mt = 0; mt < 2; mt++)
#pragma unroll
                    for (int nt = 0; nt < 4; nt++)
#pragma unroll
                        for (int r = 0; r < 4; r++) cc[mt][nt][r] = 0.0f;

#pragma unroll
                for (int kt = 0; kt < 2; kt++) {
                    uint32_t aH[2][4], aL[2][4];
                    const int pc = 8 * kt;   // pair offset of this k16 tile
#pragma unroll
                    for (int mt = 0; mt < 2; mt++) {
                        const int R = 16 * mt;
                        aH[mt][0] = mHH[(R + g) * HSTRIDE + pc + q];
                        aH[mt][1] = mHH[(R + g + 8) * HSTRIDE + pc + q];
                        aH[mt][2] = mHH[(R + g) * HSTRIDE + pc + q + 4];
                        aH[mt][3] = mHH[(R + g + 8) * HSTRIDE + pc + q + 4];
                        aL[mt][0] = mHL[(R + g) * HSTRIDE + pc + q];
                        aL[mt][1] = mHL[(R + g + 8) * HSTRIDE + pc + q];
                        aL[mt][2] = mHL[(R + g) * HSTRIDE + pc + q + 4];
                        aL[mt][3] = mHL[(R + g + 8) * HSTRIDE + pc + q + 4];
                    }
#pragma unroll
                    for (int nt = 0; nt < 4; nt++) {
                        uint4 wv = WF4[((d * 2 + kt) * 32 + lane) * 4 + nt];
#pragma unroll
                        for (int mt = 0; mt < 2; mt++) {
                            mma_f16(cc[mt][nt], aH[mt][0], aH[mt][1], aH[mt][2], aH[mt][3], wv.x, wv.y);
                            mma_f16(cc[mt][nt], aL[mt][0], aL[mt][1], aL[mt][2], aL[mt][3], wv.x, wv.y);
                            mma_f16(cc[mt][nt], aH[mt][0], aH[mt][1], aH[mt][2], aH[mt][3], wv.z, wv.w);
                        }
                    }
                }

                __syncwarp();
#pragma unroll
                for (int mt = 0; mt < 2; mt++)
#pragma unroll
                    for (int nt = 0; nt < 4; nt++)
#pragma unroll
                        for (int rh = 0; rh < 2; rh++) {
                            int c0 = 8 * nt + 2 * q;
                            float v0 = fmaxf(cc[mt][nt][2 * rh]     + bsd[d * WD + c0],     0.0f);
                            float v1 = fmaxf(cc[mt][nt][2 * rh + 1] + bsd[d * WD + c0 + 1], 0.0f);
                            if (d < DEPTH - 1) {
                                int rowl = 16 * mt + g + 8 * rh;
                                uint32_t hi2, lo2;
                                split_h2(v0, v1, hi2, lo2);
                                mHH[rowl * HSTRIDE + 4 * nt + q] = hi2;
                                mHL[rowl * HSTRIDE + 4 * nt + q] = lo2;
                            } else {
                                acc[mt * 2 + rh] = fmaf(v0, wo[nt * 2 + 0],
                                                   fmaf(v1, wo[nt * 2 + 1], acc[mt * 2 + rh]));
                            }
                        }
                __syncwarp();
            }

            // ---- output reduce across the 4-lane column group ----
#pragma unroll
            for (int jj = 0; jj < 4; jj++) {
                acc[jj] += __shfl_xor_sync(0xFFFFFFFFu, acc[jj], 1);
                acc[jj] += __shfl_xor_sync(0xFFFFFFFFu, acc[jj], 2);
            }
            if (q == 0) {
#pragma unroll
                for (int jj = 0; jj < 4; jj++) {
                    int rowl = 16 * (jj >> 1) + g + 8 * (jj & 1);
                    int pt = myxp[rowl];
                    if (pt >= 0) out[pt] = acc[jj] + boutv;
                }
            }
        }
    }

    // replay-state reset: last block out resets everything
    __syncthreads();
    if (tid == 0) {
        int old = atomicAdd(&g_done, 1);
        if (old == (int)gridDim.x - 1) {
            g_nact = 0;
            float* s = &g_img_sum[0][0];
            for (int t = 0; t < BB * WD; t++) s[t] = 0.0f;
            for (int t = 0; t < BB; t++) g_img_cnt[t] = 0.0f;
            __threadfence();
            g_done = 0;
        }
    }
}

// ---------------------------------------------------------------------------
extern "C" void kernel_launch(void* const* d_in, const int* in_sizes, int n_in,
                              void* d_out, int out_size)
{
    const float* Imodel   = (const float*)d_in[0];
    const float* Iobs     = (const float*)d_in[1];
    const float* metadata = (const float*)d_in[2];
    const void*  mask     = d_in[3];
    const float* W_img_in = (const float*)d_in[5];
    const float* b_img_in = (const float*)d_in[6];
    const float* W_img    = (const float*)d_in[7];
    const float* b_img    = (const float*)d_in[8];
    const float* W_lin_in = (const float*)d_in[9];
    const float* b_lin_in = (const float*)d_in[10];
    const float* W_mlp    = (const float*)d_in[11];
    const float* b_mlp    = (const float*)d_in[12];
    const float* W_out    = (const float*)d_in[13];
    const float* b_out    = (const float*)d_in[14];
    float* out = (float*)d_out;

    static int smem_set = 0;
    if (!smem_set) {
        cudaFuncSetAttribute(k_main, cudaFuncAttributeMaxDynamicSharedMemorySize,
                             SMEM_BYTES);
        smem_set = 1;
    }

    k_front<<<IMGB + NCOMPB, 256>>>(mask, Imodel, Iobs, metadata,
                                    W_img_in, b_img_in, W_img, b_img, out);
    k_main<<<NMAINB, MT_TPB, SMEM_BYTES>>>(metadata, W_lin_in, b_lin_in,
                                           W_mlp, b_mlp, W_out, b_out, out);
}

// round 14
// speedup vs baseline: 1.1587x; 1.1232x over previous
#include <cuda_runtime.h>
#include <cuda_fp16.h>
#include <math.h>
#include <stdint.h>
#include <string.h>

// Problem constants
#define BB     16
#define JJ     256
#define KK     384
#define CMETA  6
#define CIN    8
#define WD     32
#define DEPTH  3
#define SS     32
#define JK     (JJ*KK)        // 98304
#define NPTS   (BB*JK)        // 1572864

// tensor k_main config
#define MT_TPB   128          // 4 warps
#define MT_ROWS  128
#define MT_ITERS 4
#define MT_PTSBLK (MT_ROWS*MT_ITERS)   // 512
#define NMAINB  (NPTS/MT_PTSBLK)       // 3072

// front kernel: image blocks first, then compaction blocks
#define RPB   4
#define IMGB  (BB*(SS/RPB))      // 128 image blocks (4 rows each)
#define ITB   192                // compute threads for image MLP (2 pts each)
#define CB    256
#define CPT   4
#define NCOMPB (NPTS/(CB*CPT))   // 1536

// k_main dynamic SMEM layout
#define WF4_N   (3*2*32*4)       // 768 uint4 (hidden-layer B frags)
#define WF0_N   (32*4)           // 128 uint2 (input-layer B frags)
#define HSTRIDE 20               // uint32 stride per row (16 pairs + pad)
#define HROW_N  (4*32*HSTRIDE)   // per hi/lo array
#define SMEM_BYTES (WF4_N*16 + WF0_N*8 + 2*HROW_N*4 + (BB*WD + DEPTH*WD + WD + 4)*4 + 2*128*4 + 256)

// Scratch (device globals; zero at module load; k_main's last block re-zeros)
__device__ float g_img_sum[BB][WD];
__device__ float g_img_cnt[BB];
__device__ int   g_nact;
__device__ int   g_done;
__device__ int   g_idx[NPTS];

__device__ __forceinline__ bool mask_at(const void* m, int fmt, int i) {
    if (fmt == 0) return ((const unsigned char*)m)[i] != 0;
    if (fmt == 1) return ((const int*)m)[i] != 0;
    return ((const float*)m)[i] != 0.0f;
}

__device__ __forceinline__ int detect_fmt_block(const void* mask) {
    unsigned int v = ((const unsigned int*)mask)[threadIdx.x & 255];
    int all_int = __syncthreads_and(v <= 1u);
    int all_flt = __syncthreads_and(v == 0u || v == 0x3F800000u);
    return all_int ? 1 : (all_flt ? 2 : 0);
}

__device__ __forceinline__ unsigned int rotl32(unsigned int x, int r) {
    return (x << r) | (x >> (32 - r));
}

// ---- fp16 split helpers ----
__device__ __forceinline__ uint32_t h2u(__half2 h) {
    uint32_t u; memcpy(&u, &h, 4); return u;
}
__device__ __forceinline__ void split_h2(float v0, float v1,
                                         uint32_t& hi2, uint32_t& lo2) {
    __half2 h = __floats2half2_rn(v0, v1);          // low=v0, high=v1
    float e0 = __low2float(h);
    float e1 = __high2float(h);
    __half2 l = __floats2half2_rn(v0 - e0, v1 - e1);
    hi2 = h2u(h); lo2 = h2u(l);
}
__device__ __forceinline__ void mma_f16(float c[4],
                                        uint32_t a0, uint32_t a1, uint32_t a2, uint32_t a3,
                                        uint32_t b0, uint32_t b1) {
    asm("mma.sync.aligned.m16n8k16.row.col.f32.f16.f16.f32 "
        "{%0,%1,%2,%3},{%4,%5,%6,%7},{%8,%9},{%0,%1,%2,%3};"
        : "+f"(c[0]), "+f"(c[1]), "+f"(c[2]), "+f"(c[3])
        : "r"(a0), "r"(a1), "r"(a2), "r"(a3), "r"(b0), "r"(b1));
}

// ---------------------------------------------------------------------------
// Front kernel: blocks [0,IMGB) = image branch with LOCAL gumbel selection
// (RPB=4 rows per block); blocks [IMGB,..) = stream compaction.
// ---------------------------------------------------------------------------
__global__ void __launch_bounds__(256) k_front(
    const void* __restrict__ mask,
    const float* __restrict__ Imodel, const float* __restrict__ Iobs,
    const float* __restrict__ metadata,
    const float* __restrict__ W_img_in, const float* __restrict__ b_img_in,
    const float* __restrict__ W_img, const float* __restrict__ b_img,
    float* __restrict__ out)
{
    const int fmt = detect_fmt_block(mask);
    const int tid = threadIdx.x;

    if (blockIdx.x >= IMGB) {
        // ---------------- compaction role ----------------
        const int cb = blockIdx.x - IMGB;
        const int lane = tid & 31;
        const int wid = tid >> 5;
        const unsigned int lt = (1u << lane) - 1u;
        const int base = cb * CB * CPT;

        bool act[CPT];
        unsigned int bal[CPT];
        int wcnt = 0;
#pragma unroll
        for (int r = 0; r < CPT; r++) {
            const int p = base + r * CB + tid;
            act[r] = mask_at(mask, fmt, p);
            bal[r] = __ballot_sync(0xFFFFFFFFu, act[r]);
            wcnt += __popc(bal[r]);
            if (!act[r]) out[p] = 0.0f;
        }

        __shared__ int wsum[8];
        __shared__ int bbase;
        if (lane == 0) wsum[wid] = wcnt;
        __syncthreads();
        if (tid == 0) {
            int tot = 0;
#pragma unroll
            for (int w = 0; w < 8; w++) { int c = wsum[w]; wsum[w] = tot; tot += c; }
            bbase = atomicAdd(&g_nact, tot);
        }
        __syncthreads();

        int off = bbase + wsum[wid];
#pragma unroll
        for (int r = 0; r < CPT; r++) {
            if (act[r]) g_idx[off + __popc(bal[r] & lt)] = base + r * CB + tid;
            off += __popc(bal[r]);
        }
        return;
    }

    // ---------------- image role (local selection, RPB rows) ----------------
    const int b = blockIdx.x / (SS / RPB);
    const int s0 = (blockIdx.x % (SS / RPB)) * RPB;

    __shared__ unsigned int keys[JJ];
    __shared__ int selrows[RPB];
    __shared__ __align__(16) float W0s[WD * CIN];
    __shared__ __align__(16) float Ws[DEPTH * WD * WD];
    __shared__ float bs0[WD];
    __shared__ float bsd[DEPTH][WD];

    {
        const int j = tid;
        const int rbase = (b * JJ + j) * KK;
        bool alive = false;
        for (int k = 0; k < KK; k++) {
            if (mask_at(mask, fmt, rbase + k)) { alive = true; break; }
        }

        const unsigned int n = (unsigned int)(b * JJ + j);
        unsigned int x0 = 0u;
        unsigned int x1 = n;
        const unsigned int ks0 = 0u;
        const unsigned int ks1 = 42u;
        const unsigned int ks2 = 0x1BD11BDAu ^ 42u;
        x0 += ks0; x1 += ks1;
#define TF_ROUND(r) { x0 += x1; x1 = rotl32(x1, (r)); x1 ^= x0; }
        TF_ROUND(13) TF_ROUND(15) TF_ROUND(26) TF_ROUND(6)
        x0 += ks1; x1 += ks2 + 1u;
        TF_ROUND(17) TF_ROUND(29) TF_ROUND(16) TF_ROUND(24)
        x0 += ks2; x1 += ks0 + 2u;
        TF_ROUND(13) TF_ROUND(15) TF_ROUND(26) TF_ROUND(6)
        x0 += ks0; x1 += ks1 + 3u;
        TF_ROUND(17) TF_ROUND(29) TF_ROUND(16) TF_ROUND(24)
        x0 += ks1; x1 += ks2 + 4u;
        TF_ROUND(13) TF_ROUND(15) TF_ROUND(26) TF_ROUND(6)
        x0 += ks2; x1 += ks0 + 5u;
#undef TF_ROUND
        const unsigned int bits = x0 ^ x1;
        const unsigned int keyv = alive ? ((bits >> 9) | 0x80000000u) : 0u;
        keys[j] = keyv;
        __syncthreads();

        int rank = 0;
        for (int t = 0; t < JJ; t++) {
            unsigned int s = keys[t];
            if (s > keyv || (s == keyv && t < j)) rank++;
        }
        if (rank >= s0 && rank < s0 + RPB) selrows[rank - s0] = j;
    }

    for (int t = tid; t < CIN * WD; t += 256) {
        int i = t / WD, c = t % WD;
        W0s[c * CIN + i] = W_img_in[t];
    }
    for (int t = tid; t < DEPTH * WD * WD; t += 256) {
        int d = t / (WD * WD); int r = t % (WD * WD); int i = r / WD, c = r % WD;
        Ws[(d * WD + c) * WD + i] = W_img[t];
    }
    for (int t = tid; t < WD; t += 256) bs0[t] = b_img_in[t];
    for (int t = tid; t < DEPTH * WD; t += 256) bsd[t / WD][t % WD] = b_img[t];
    __syncthreads();

    if (tid >= ITB) return;

#pragma unroll 1
    for (int rr = 0; rr < RPB; rr++) {
        const int j = selrows[rr];
        const int base = (b * JJ + j) * KK;
        const int pA = base + tid;
        const int pB = base + tid + ITB;

        float x0[CIN], x1[CIN];
        x0[0] = Imodel[pA]; x1[0] = Imodel[pB];
        x0[1] = Iobs[pA];   x1[1] = Iobs[pB];
        {
            const float* m0 = metadata + (size_t)pA * CMETA;
            const float* m1 = metadata + (size_t)pB * CMETA;
#pragma unroll
            for (int i = 0; i < CMETA; i++) { x0[2 + i] = m0[i]; x1[2 + i] = m1[i]; }
        }

        float h0[WD], h1[WD], o0[WD], o1[WD];

#pragma unroll
        for (int c = 0; c < WD; c++) {
            float a0 = bs0[c], a1 = a0;
            const float4* wr = (const float4*)&W0s[c * CIN];
#pragma unroll
            for (int i4 = 0; i4 < 2; i4++) {
                float4 w = wr[i4];
                a0 = fmaf(x0[i4 * 4 + 0], w.x, a0);
                a0 = fmaf(x0[i4 * 4 + 1], w.y, a0);
                a0 = fmaf(x0[i4 * 4 + 2], w.z, a0);
                a0 = fmaf(x0[i4 * 4 + 3], w.w, a0);
                a1 = fmaf(x1[i4 * 4 + 0], w.x, a1);
                a1 = fmaf(x1[i4 * 4 + 1], w.y, a1);
                a1 = fmaf(x1[i4 * 4 + 2], w.z, a1);
                a1 = fmaf(x1[i4 * 4 + 3], w.w, a1);
            }
            h0[c] = a0; h1[c] = a1;
        }

#pragma unroll 1
        for (int d = 0; d < DEPTH; d++) {
            const float4* wl = (const float4*)&Ws[d * WD * WD];
#pragma unroll
            for (int c = 0; c < WD; c++) {
                float a0 = bsd[d][c], a1 = a0;
#pragma unroll
                for (int i4 = 0; i4 < 8; i4++) {
                    float4 w = wl[c * 8 + i4];
                    a0 = fmaf(h0[i4 * 4 + 0], w.x, a0);
                    a0 = fmaf(h0[i4 * 4 + 1], w.y, a0);
                    a0 = fmaf(h0[i4 * 4 + 2], w.z, a0);
                    a0 = fmaf(h0[i4 * 4 + 3], w.w, a0);
                    a1 = fmaf(h1[i4 * 4 + 0], w.x, a1);
                    a1 = fmaf(h1[i4 * 4 + 1], w.y, a1);
                    a1 = fmaf(h1[i4 * 4 + 2], w.z, a1);
                    a1 = fmaf(h1[i4 * 4 + 3], w.w, a1);
                }
                o0[c] = fmaxf(a0, 0.0f);
                o1[c] = fmaxf(a1, 0.0f);
            }
#pragma unroll
            for (int c = 0; c < WD; c++) { h0[c] = o0[c]; h1[c] = o1[c]; }
        }

        const float m0 = mask_at(mask, fmt, pA) ? 1.0f : 0.0f;
        const float m1 = mask_at(mask, fmt, pB) ? 1.0f : 0.0f;

#pragma unroll
        for (int c = 0; c < WD; c++) {
            float v = m0 * h0[c] + m1 * h1[c];
#pragma unroll
            for (int o = 16; o > 0; o >>= 1) v += __shfl_xor_sync(0xFFFFFFFFu, v, o);
            if ((tid & 31) == 0) atomicAdd(&g_img_sum[b][c], v);
        }
        {
            float v = m0 + m1;
#pragma unroll
            for (int o = 16; o > 0; o >>= 1) v += __shfl_xor_sync(0xFFFFFFFFu, v, o);
            if ((tid & 31) == 0) atomicAdd(&g_img_cnt[b], v);
        }
    }
}

// ---------------------------------------------------------------------------
// Kernel 2: main branch on tensor cores — fp16 m16n8k16 Markidis 3-pass.
// ---------------------------------------------------------------------------
__global__ void __launch_bounds__(MT_TPB, 4) k_main(
    const float* __restrict__ metadata,
    const float* __restrict__ W_lin_in, const float* __restrict__ b_lin_in,
    const float* __restrict__ W_mlp, const float* __restrict__ b_mlp,
    const float* __restrict__ W_out, const float* __restrict__ b_out,
    float* __restrict__ out)
{
    extern __shared__ __align__(16) unsigned char dynsmem[];
    uint4* WF4   = (uint4*)dynsmem;
    uint2* WF0   = (uint2*)(WF4 + WF4_N);
    uint32_t* HH = (uint32_t*)(WF0 + WF0_N);
    uint32_t* HL = HH + HROW_N;
    float* beffs = (float*)(HL + HROW_N);
    float* bsd   = beffs + BB * WD;
    float* wout_s= bsd + DEPTH * WD;
    float* bout_s= wout_s + WD;
    int*   xb    = (int*)(bout_s + 4);
    int*   xp    = xb + 128;

    const int tid = threadIdx.x;

    for (int t = tid; t < 3 * 2 * 32 * 4; t += MT_TPB) {
        int nt = t & 3, lane = (t >> 2) & 31, kt = (t >> 7) & 1, d = t >> 8;
        int n = (lane >> 2) + 8 * nt;
        int k0 = 2 * (lane & 3) + 16 * kt;
        uint32_t b0h, b0l, b1h, b1l;
        split_h2(W_mlp[(d * WD + k0) * WD + n],     W_mlp[(d * WD + k0 + 1) * WD + n], b0h, b0l);
        split_h2(W_mlp[(d * WD + k0 + 8) * WD + n], W_mlp[(d * WD + k0 + 9) * WD + n], b1h, b1l);
        WF4[((d * 2 + kt) * 32 + lane) * 4 + nt] = make_uint4(b0h, b1h, b0l, b1l);
    }
    for (int t = tid; t < 32 * 4; t += MT_TPB) {
        int nt = t & 3, lane = t >> 2;
        int n = (lane >> 2) + 8 * nt;
        int k0 = 2 * (lane & 3);
        float w0 = (k0 < CMETA) ? W_lin_in[k0 * WD + n] : 0.0f;
        float w1 = (k0 + 1 < CMETA) ? W_lin_in[(k0 + 1) * WD + n] : 0.0f;
        uint32_t bh, bl;
        split_h2(w0, w1, bh, bl);
        WF0[lane * 4 + nt] = make_uint2(bh, bl);
    }
    for (int t = tid; t < BB * WD; t += MT_TPB) {
        int bb = t / WD, c = t % WD;
        beffs[t] = b_lin_in[c] + g_img_sum[bb][c] / g_img_cnt[bb];
    }
    for (int t = tid; t < DEPTH * WD; t += MT_TPB) bsd[t] = b_mlp[t];
    if (tid < WD) wout_s[tid] = W_out[tid];
    if (tid == 0) bout_s[0] = b_out[0];
    __syncthreads();

    const int n_act = g_nact;
    const int w = tid >> 5;
    const int lane = tid & 31;
    const int g = lane >> 2;
    const int q = lane & 3;
    const int blkbase = blockIdx.x * MT_PTSBLK;

    float wo[8];
#pragma unroll
    for (int nt = 0; nt < 4; nt++) {
        wo[nt * 2 + 0] = wout_s[8 * nt + 2 * q + 0];
        wo[nt * 2 + 1] = wout_s[8 * nt + 2 * q + 1];
    }
    const float boutv = bout_s[0];
    uint32_t* mHH = HH + w * 32 * HSTRIDE;
    uint32_t* mHL = HL + w * 32 * HSTRIDE;
    int* myxb = xb + w * 32;
    int* myxp = xp + w * 32;

    if (blkbase < n_act) {
#pragma unroll 1
        for (int it = 0; it < MT_ITERS; it++) {
            if (blkbase + it * MT_ROWS >= n_act) break;
            const int slot = blkbase + it * MT_ROWS + tid;
            const bool valid = slot < n_act;
            const int p = valid ? g_idx[slot] : 0;

            __syncwarp();
            {
                const float* mp = metadata + (size_t)p * CMETA;
                float xv[8];
#pragma unroll
                for (int i = 0; i < CMETA; i++) xv[i] = mp[i];
                xv[6] = 0.0f; xv[7] = 0.0f;
                uint32_t* hr = mHH + lane * HSTRIDE;
                uint32_t* lr = mHL + lane * HSTRIDE;
#pragma unroll
                for (int pr = 0; pr < 4; pr++) {
                    uint32_t hi2, lo2;
                    split_h2(xv[2 * pr], xv[2 * pr + 1], hi2, lo2);
                    hr[pr] = hi2; lr[pr] = lo2;
                }
                myxb[lane] = p / JK;
                myxp[lane] = valid ? p : -1;
            }
            __syncwarp();

            const int b4[4] = { myxb[g], myxb[g + 8], myxb[g + 16], myxb[g + 24] };

            float cc[2][4][4];
#pragma unroll
            for (int mt = 0; mt < 2; mt++)
#pragma unroll
                for (int nt = 0; nt < 4; nt++)
#pragma unroll
                    for (int r = 0; r < 4; r++) cc[mt][nt][r] = 0.0f;

            {
                uint32_t aH[2][2], aL[2][2];
#pragma unroll
                for (int mt = 0; mt < 2; mt++) {
                    const int R = 16 * mt;
                    aH[mt][0] = mHH[(R + g) * HSTRIDE + q];
                    aH[mt][1] = mHH[(R + g + 8) * HSTRIDE + q];
                    aL[mt][0] = mHL[(R + g) * HSTRIDE + q];
                    aL[mt][1] = mHL[(R + g + 8) * HSTRIDE + q];
                }
#pragma unroll
                for (int nt = 0; nt < 4; nt++) {
                    uint2 wv = WF0[lane * 4 + nt];
#pragma unroll
                    for (int mt = 0; mt < 2; mt++) {
                        mma_f16(cc[mt][nt], aH[mt][0], aH[mt][1], 0u, 0u, wv.x, 0u);
                        mma_f16(cc[mt][nt], aL[mt][0], aL[mt][1], 0u, 0u, wv.x, 0u);
                        mma_f16(cc[mt][nt], aH[mt][0], aH[mt][1], 0u, 0u, wv.y, 0u);
                    }
                }
            }

            __syncwarp();
#pragma unroll
            for (int mt = 0; mt < 2; mt++)
#pragma unroll
                for (int nt = 0; nt < 4; nt++)
#pragma unroll
                    for (int rh = 0; rh < 2; rh++) {
                        int rowl = 16 * mt + g + 8 * rh;
                        int c0 = 8 * nt + 2 * q;
                        int bi = b4[mt * 2 + rh];
                        float v0 = cc[mt][nt][2 * rh]     + beffs[bi * WD + c0];
                        float v1 = cc[mt][nt][2 * rh + 1] + beffs[bi * WD + c0 + 1];
                        uint32_t hi2, lo2;
                        split_h2(v0, v1, hi2, lo2);
                        mHH[rowl * HSTRIDE + 4 * nt + q] = hi2;
                        mHL[rowl * HSTRIDE + 4 * nt + q] = lo2;
                    }
            __syncwarp();

            float acc[4] = {0.0f, 0.0f, 0.0f, 0.0f};
#pragma unroll
            for (int d = 0; d < DEPTH; d++) {
#pragma unroll
                for (int mt = 0; mt < 2; mt++)
#pragma unroll
                    for (int nt = 0; nt < 4; nt++)
#pragma unroll
                        for (int r = 0; r < 4; r++) cc[mt][nt][r] = 0.0f;

#pragma unroll
                for (int kt = 0; kt < 2; kt++) {
                    uint32_t aH[2][4], aL[2][4];
                    const int pc = 8 * kt;
#pragma unroll
                    for (int mt = 0; mt < 2; mt++) {
                        const int R = 16 * mt;
                        aH[mt][0] = mHH[(R + g) * HSTRIDE + pc + q];
                        aH[mt][1] = mHH[(R + g + 8) * HSTRIDE + pc + q];
                        aH[mt][2] = mHH[(R + g) * HSTRIDE + pc + q + 4];
                        aH[mt][3] = mHH[(R + g + 8) * HSTRIDE + pc + q + 4];
                        aL[mt][0] = mHL[(R + g) * HSTRIDE + pc + q];
                        aL[mt][1] = mHL[(R + g + 8) * HSTRIDE + pc + q];
                        aL[mt][2] = mHL[(R + g) * HSTRIDE + pc + q + 4];
                        aL[mt][3] = mHL[(R + g + 8) * HSTRIDE + pc + q + 4];
                    }
#pragma unroll
                    for (int nt = 0; nt < 4; nt++) {
                        uint4 wv = WF4[((d * 2 + kt) * 32 + lane) * 4 + nt];
#pragma unroll
                        for (int mt = 0; mt < 2; mt++) {
                            mma_f16(cc[mt][nt], aH[mt][0], aH[mt][1], aH[mt][2], aH[mt][3], wv.x, wv.y);
                            mma_f16(cc[mt][nt], aL[mt][0], aL[mt][1], aL[mt][2], aL[mt][3], wv.x, wv.y);
                            mma_f16(cc[mt][nt], aH[mt][0], aH[mt][1], aH[mt][2], aH[mt][3], wv.z, wv.w);
                        }
                    }
                }

                __syncwarp();
#pragma unroll
                for (int mt = 0; mt < 2; mt++)
#pragma unroll
                    for (int nt = 0; nt < 4; nt++)
#pragma unroll
                        for (int rh = 0; rh < 2; rh++) {
                            int c0 = 8 * nt + 2 * q;
                            float v0 = fmaxf(cc[mt][nt][2 * rh]     + bsd[d * WD + c0],     0.0f);
                            float v1 = fmaxf(cc[mt][nt][2 * rh + 1] + bsd[d * WD + c0 + 1], 0.0f);
                            if (d < DEPTH - 1) {
                                int rowl = 16 * mt + g + 8 * rh;
                                uint32_t hi2, lo2;
                                split_h2(v0, v1, hi2, lo2);
                                mHH[rowl * HSTRIDE + 4 * nt + q] = hi2;
                                mHL[rowl * HSTRIDE + 4 * nt + q] = lo2;
                            } else {
                                acc[mt * 2 + rh] = fmaf(v0, wo[nt * 2 + 0],
                                                   fmaf(v1, wo[nt * 2 + 1], acc[mt * 2 + rh]));
                            }
                        }
                __syncwarp();
            }

#pragma unroll
            for (int jj = 0; jj < 4; jj++) {
                acc[jj] += __shfl_xor_sync(0xFFFFFFFFu, acc[jj], 1);
                acc[jj] += __shfl_xor_sync(0xFFFFFFFFu, acc[jj], 2);
            }
            if (q == 0) {
#pragma unroll
                for (int jj = 0; jj < 4; jj++) {
                    int rowl = 16 * (jj >> 1) + g + 8 * (jj & 1);
                    int pt = myxp[rowl];
                    if (pt >= 0) out[pt] = acc[jj] + boutv;
                }
            }
        }
    }

    __syncthreads();
    if (tid == 0) {
        int old = atomicAdd(&g_done, 1);
        if (old == (int)gridDim.x - 1) {
            g_nact = 0;
            float* s = &g_img_sum[0][0];
            for (int t = 0; t < BB * WD; t++) s[t] = 0.0f;
            for (int t = 0; t < BB; t++) g_img_cnt[t] = 0.0f;
            __threadfence();
            g_done = 0;
        }
    }
}

// ---------------------------------------------------------------------------
extern "C" void kernel_launch(void* const* d_in, const int* in_sizes, int n_in,
                              void* d_out, int out_size)
{
    const float* Imodel   = (const float*)d_in[0];
    const float* Iobs     = (const float*)d_in[1];
    const float* metadata = (const float*)d_in[2];
    const void*  mask     = d_in[3];
    const float* W_img_in = (const float*)d_in[5];
    const float* b_img_in = (const float*)d_in[6];
    const float* W_img    = (const float*)d_in[7];
    const float* b_img    = (const float*)d_in[8];
    const float* W_lin_in = (const float*)d_in[9];
    const float* b_lin_in = (const float*)d_in[10];
    const float* W_mlp    = (const float*)d_in[11];
    const float* b_mlp    = (const float*)d_in[12];
    const float* W_out    = (const float*)d_in[13];
    const float* b_out    = (const float*)d_in[14];
    float* out = (float*)d_out;

    static int smem_set = 0;
    if (!smem_set) {
        cudaFuncSetAttribute(k_main, cudaFuncAttributeMaxDynamicSharedMemorySize,
                             SMEM_BYTES);
        smem_set = 1;
    }

    k_front<<<IMGB + NCOMPB, 256>>>(mask, Imodel, Iobs, metadata,
                                    W_img_in, b_img_in, W_img, b_img, out);
    k_main<<<NMAINB, MT_TPB, SMEM_BYTES>>>(metadata, W_lin_in, b_lin_in,
                                           W_mlp, b_mlp, W_out, b_out, out);
}

// round 15
// speedup vs baseline: 1.4896x; 1.2856x over previous
#include <cuda_runtime.h>
#include <cuda_fp16.h>
#include <math.h>
#include <stdint.h>
#include <string.h>

// Problem constants
#define BB     16
#define JJ     256
#define KK     384
#define CMETA  6
#define CIN    8
#define WD     32
#define DEPTH  3
#define SS     32
#define JK     (JJ*KK)        // 98304
#define NPTS   (BB*JK)        // 1572864

// tensor k_main config
#define MT_TPB   128          // 4 warps
#define MT_ROWS  128
#define MT_ITERS 4
#define MT_PTSBLK (MT_ROWS*MT_ITERS)   // 512
#define NMAINB  (NPTS/MT_PTSBLK)       // 3072

// front kernel: image blocks first, then compaction blocks
#define RPB   4
#define IMGB  (BB*(SS/RPB))      // 128 image blocks (4 rows each)
#define ITB   192                // compute threads for image MLP (2 pts each)
#define CB    256
#define CPT   4
#define NCOMPB (NPTS/(CB*CPT))   // 1536

// k_main dynamic SMEM layout
#define WF4_N   (3*2*4*32)       // 768 uint4, [dkt][nt][lane] lane-contiguous
#define WF0_N   (4*32)           // 128 uint2, [nt][lane]
#define XS_N    (4*32*9)         // staged input rows, stride 9 floats
#define SMEM_BYTES (WF4_N*16 + WF0_N*8 + XS_N*4 + (BB*WD + DEPTH*WD + WD + 4)*4 + 2*128*4 + 256)

// Scratch (device globals; zero at module load; k_main's last block re-zeros)
__device__ float g_img_sum[BB][WD];
__device__ float g_img_cnt[BB];
__device__ int   g_nact;
__device__ int   g_done;
__device__ int   g_idx[NPTS];

__device__ __forceinline__ bool mask_at(const void* m, int fmt, int i) {
    if (fmt == 0) return ((const unsigned char*)m)[i] != 0;
    if (fmt == 1) return ((const int*)m)[i] != 0;
    return ((const float*)m)[i] != 0.0f;
}

__device__ __forceinline__ int detect_fmt_block(const void* mask) {
    unsigned int v = ((const unsigned int*)mask)[threadIdx.x & 255];
    int all_int = __syncthreads_and(v <= 1u);
    int all_flt = __syncthreads_and(v == 0u || v == 0x3F800000u);
    return all_int ? 1 : (all_flt ? 2 : 0);
}

__device__ __forceinline__ unsigned int rotl32(unsigned int x, int r) {
    return (x << r) | (x >> (32 - r));
}

// ---- fp16 split helpers ----
__device__ __forceinline__ uint32_t h2u(__half2 h) {
    uint32_t u; memcpy(&u, &h, 4); return u;
}
__device__ __forceinline__ void split_h2(float v0, float v1,
                                         uint32_t& hi2, uint32_t& lo2) {
    __half2 h = __floats2half2_rn(v0, v1);
    float e0 = __low2float(h);
    float e1 = __high2float(h);
    __half2 l = __floats2half2_rn(v0 - e0, v1 - e1);
    hi2 = h2u(h); lo2 = h2u(l);
}
__device__ __forceinline__ void mma_f16(float c[4],
                                        uint32_t a0, uint32_t a1, uint32_t a2, uint32_t a3,
                                        uint32_t b0, uint32_t b1) {
    asm("mma.sync.aligned.m16n8k16.row.col.f32.f16.f16.f32 "
        "{%0,%1,%2,%3},{%4,%5,%6,%7},{%8,%9},{%0,%1,%2,%3};"
        : "+f"(c[0]), "+f"(c[1]), "+f"(c[2]), "+f"(c[3])
        : "r"(a0), "r"(a1), "r"(a2), "r"(a3), "r"(b0), "r"(b1));
}

// ---------------------------------------------------------------------------
// Front kernel: blocks [0,IMGB) = image branch with LOCAL gumbel selection
// (RPB=4 rows per block); blocks [IMGB,..) = stream compaction.
// ---------------------------------------------------------------------------
__global__ void __launch_bounds__(256) k_front(
    const void* __restrict__ mask,
    const float* __restrict__ Imodel, const float* __restrict__ Iobs,
    const float* __restrict__ metadata,
    const float* __restrict__ W_img_in, const float* __restrict__ b_img_in,
    const float* __restrict__ W_img, const float* __restrict__ b_img,
    float* __restrict__ out)
{
    const int fmt = detect_fmt_block(mask);
    const int tid = threadIdx.x;

    if (blockIdx.x >= IMGB) {
        const int cb = blockIdx.x - IMGB;
        const int lane = tid & 31;
        const int wid = tid >> 5;
        const unsigned int lt = (1u << lane) - 1u;
        const int base = cb * CB * CPT;

        bool act[CPT];
        unsigned int bal[CPT];
        int wcnt = 0;
#pragma unroll
        for (int r = 0; r < CPT; r++) {
            const int p = base + r * CB + tid;
            act[r] = mask_at(mask, fmt, p);
            bal[r] = __ballot_sync(0xFFFFFFFFu, act[r]);
            wcnt += __popc(bal[r]);
            if (!act[r]) out[p] = 0.0f;
        }

        __shared__ int wsum[8];
        __shared__ int bbase;
        if (lane == 0) wsum[wid] = wcnt;
        __syncthreads();
        if (tid == 0) {
            int tot = 0;
#pragma unroll
            for (int w = 0; w < 8; w++) { int c = wsum[w]; wsum[w] = tot; tot += c; }
            bbase = atomicAdd(&g_nact, tot);
        }
        __syncthreads();

        int off = bbase + wsum[wid];
#pragma unroll
        for (int r = 0; r < CPT; r++) {
            if (act[r]) g_idx[off + __popc(bal[r] & lt)] = base + r * CB + tid;
            off += __popc(bal[r]);
        }
        return;
    }

    // ---------------- image role (local selection, RPB rows) ----------------
    const int b = blockIdx.x / (SS / RPB);
    const int s0 = (blockIdx.x % (SS / RPB)) * RPB;

    __shared__ unsigned int keys[JJ];
    __shared__ int selrows[RPB];
    __shared__ __align__(16) float W0s[WD * CIN];
    __shared__ __align__(16) float Ws[DEPTH * WD * WD];
    __shared__ float bs0[WD];
    __shared__ float bsd[DEPTH][WD];

    {
        const int j = tid;
        const int rbase = (b * JJ + j) * KK;
        bool alive = false;
        for (int k = 0; k < KK; k++) {
            if (mask_at(mask, fmt, rbase + k)) { alive = true; break; }
        }

        const unsigned int n = (unsigned int)(b * JJ + j);
        unsigned int x0 = 0u;
        unsigned int x1 = n;
        const unsigned int ks0 = 0u;
        const unsigned int ks1 = 42u;
        const unsigned int ks2 = 0x1BD11BDAu ^ 42u;
        x0 += ks0; x1 += ks1;
#define TF_ROUND(r) { x0 += x1; x1 = rotl32(x1, (r)); x1 ^= x0; }
        TF_ROUND(13) TF_ROUND(15) TF_ROUND(26) TF_ROUND(6)
        x0 += ks1; x1 += ks2 + 1u;
        TF_ROUND(17) TF_ROUND(29) TF_ROUND(16) TF_ROUND(24)
        x0 += ks2; x1 += ks0 + 2u;
        TF_ROUND(13) TF_ROUND(15) TF_ROUND(26) TF_ROUND(6)
        x0 += ks0; x1 += ks1 + 3u;
        TF_ROUND(17) TF_ROUND(29) TF_ROUND(16) TF_ROUND(24)
        x0 += ks1; x1 += ks2 + 4u;
        TF_ROUND(13) TF_ROUND(15) TF_ROUND(26) TF_ROUND(6)
        x0 += ks2; x1 += ks0 + 5u;
#undef TF_ROUND
        const unsigned int bits = x0 ^ x1;
        const unsigned int keyv = alive ? ((bits >> 9) | 0x80000000u) : 0u;
        keys[j] = keyv;
        __syncthreads();

        int rank = 0;
        for (int t = 0; t < JJ; t++) {
            unsigned int s = keys[t];
            if (s > keyv || (s == keyv && t < j)) rank++;
        }
        if (rank >= s0 && rank < s0 + RPB) selrows[rank - s0] = j;
    }

    for (int t = tid; t < CIN * WD; t += 256) {
        int i = t / WD, c = t % WD;
        W0s[c * CIN + i] = W_img_in[t];
    }
    for (int t = tid; t < DEPTH * WD * WD; t += 256) {
        int d = t / (WD * WD); int r = t % (WD * WD); int i = r / WD, c = r % WD;
        Ws[(d * WD + c) * WD + i] = W_img[t];
    }
    for (int t = tid; t < WD; t += 256) bs0[t] = b_img_in[t];
    for (int t = tid; t < DEPTH * WD; t += 256) bsd[t / WD][t % WD] = b_img[t];
    __syncthreads();

    if (tid >= ITB) return;

#pragma unroll 1
    for (int rr = 0; rr < RPB; rr++) {
        const int j = selrows[rr];
        const int base = (b * JJ + j) * KK;
        const int pA = base + tid;
        const int pB = base + tid + ITB;

        float x0[CIN], x1[CIN];
        x0[0] = Imodel[pA]; x1[0] = Imodel[pB];
        x0[1] = Iobs[pA];   x1[1] = Iobs[pB];
        {
            const float* m0 = metadata + (size_t)pA * CMETA;
            const float* m1 = metadata + (size_t)pB * CMETA;
#pragma unroll
            for (int i = 0; i < CMETA; i++) { x0[2 + i] = m0[i]; x1[2 + i] = m1[i]; }
        }

        float h0[WD], h1[WD], o0[WD], o1[WD];

#pragma unroll
        for (int c = 0; c < WD; c++) {
            float a0 = bs0[c], a1 = a0;
            const float4* wr = (const float4*)&W0s[c * CIN];
#pragma unroll
            for (int i4 = 0; i4 < 2; i4++) {
                float4 w = wr[i4];
                a0 = fmaf(x0[i4 * 4 + 0], w.x, a0);
                a0 = fmaf(x0[i4 * 4 + 1], w.y, a0);
                a0 = fmaf(x0[i4 * 4 + 2], w.z, a0);
                a0 = fmaf(x0[i4 * 4 + 3], w.w, a0);
                a1 = fmaf(x1[i4 * 4 + 0], w.x, a1);
                a1 = fmaf(x1[i4 * 4 + 1], w.y, a1);
                a1 = fmaf(x1[i4 * 4 + 2], w.z, a1);
                a1 = fmaf(x1[i4 * 4 + 3], w.w, a1);
            }
            h0[c] = a0; h1[c] = a1;
        }

#pragma unroll 1
        for (int d = 0; d < DEPTH; d++) {
            const float4* wl = (const float4*)&Ws[d * WD * WD];
#pragma unroll
            for (int c = 0; c < WD; c++) {
                float a0 = bsd[d][c], a1 = a0;
#pragma unroll
                for (int i4 = 0; i4 < 8; i4++) {
                    float4 w = wl[c * 8 + i4];
                    a0 = fmaf(h0[i4 * 4 + 0], w.x, a0);
                    a0 = fmaf(h0[i4 * 4 + 1], w.y, a0);
                    a0 = fmaf(h0[i4 * 4 + 2], w.z, a0);
                    a0 = fmaf(h0[i4 * 4 + 3], w.w, a0);
                    a1 = fmaf(h1[i4 * 4 + 0], w.x, a1);
                    a1 = fmaf(h1[i4 * 4 + 1], w.y, a1);
                    a1 = fmaf(h1[i4 * 4 + 2], w.z, a1);
                    a1 = fmaf(h1[i4 * 4 + 3], w.w, a1);
                }
                o0[c] = fmaxf(a0, 0.0f);
                o1[c] = fmaxf(a1, 0.0f);
            }
#pragma unroll
            for (int c = 0; c < WD; c++) { h0[c] = o0[c]; h1[c] = o1[c]; }
        }

        const float m0 = mask_at(mask, fmt, pA) ? 1.0f : 0.0f;
        const float m1 = mask_at(mask, fmt, pB) ? 1.0f : 0.0f;

#pragma unroll
        for (int c = 0; c < WD; c++) {
            float v = m0 * h0[c] + m1 * h1[c];
#pragma unroll
            for (int o = 16; o > 0; o >>= 1) v += __shfl_xor_sync(0xFFFFFFFFu, v, o);
            if ((tid & 31) == 0) atomicAdd(&g_img_sum[b][c], v);
        }
        {
            float v = m0 + m1;
#pragma unroll
            for (int o = 16; o > 0; o >>= 1) v += __shfl_xor_sync(0xFFFFFFFFu, v, o);
            if ((tid & 31) == 0) atomicAdd(&g_img_cnt[b], v);
        }
    }
}

// ---------------------------------------------------------------------------
// Kernel 2: fp16 Markidis tensor k_main with REGISTER-RESIDENT activations.
// C->A fragment conversion is thread-local (column-pair structures match),
// so hidden layers do NO shared-memory activation traffic.
// ---------------------------------------------------------------------------
__global__ void __launch_bounds__(MT_TPB, 4) k_main(
    const float* __restrict__ metadata,
    const float* __restrict__ W_lin_in, const float* __restrict__ b_lin_in,
    const float* __restrict__ W_mlp, const float* __restrict__ b_mlp,
    const float* __restrict__ W_out, const float* __restrict__ b_out,
    float* __restrict__ out)
{
    extern __shared__ __align__(16) unsigned char dynsmem[];
    uint4* WF4   = (uint4*)dynsmem;                 // [(d*2+kt)*4+nt][lane]
    uint2* WF0   = (uint2*)(WF4 + WF4_N);           // [nt][lane]
    float* Xs    = (float*)(WF0 + WF0_N);           // [warp][32][9]
    float* beffs = Xs + XS_N;                       // [16][32]
    float* bsd   = beffs + BB * WD;                 // [3][32]
    float* wout_s= bsd + DEPTH * WD;                // [32]
    float* bout_s= wout_s + WD;                     // [1]
    int*   xb    = (int*)(bout_s + 4);              // [4][32]
    int*   xp    = xb + 128;                        // [4][32]

    const int tid = threadIdx.x;

    // hidden-layer weight fragments, lane-contiguous (conflict-free LDS.128)
    for (int t = tid; t < WF4_N; t += MT_TPB) {     // 768
        int lane = t & 31, nt = (t >> 5) & 3, dkt = t >> 7;
        int d = dkt >> 1, kt = dkt & 1;
        int n = (lane >> 2) + 8 * nt;
        int k0 = 2 * (lane & 3) + 16 * kt;
        uint32_t b0h, b0l, b1h, b1l;
        split_h2(W_mlp[(d * WD + k0) * WD + n],     W_mlp[(d * WD + k0 + 1) * WD + n], b0h, b0l);
        split_h2(W_mlp[(d * WD + k0 + 8) * WD + n], W_mlp[(d * WD + k0 + 9) * WD + n], b1h, b1l);
        WF4[t] = make_uint4(b0h, b1h, b0l, b1l);
    }
    for (int t = tid; t < WF0_N; t += MT_TPB) {     // 128
        int lane = t & 31, nt = t >> 5;
        int n = (lane >> 2) + 8 * nt;
        int k0 = 2 * (lane & 3);
        float w0 = (k0 < CMETA) ? W_lin_in[k0 * WD + n] : 0.0f;
        float w1 = (k0 + 1 < CMETA) ? W_lin_in[(k0 + 1) * WD + n] : 0.0f;
        uint32_t bh, bl;
        split_h2(w0, w1, bh, bl);
        WF0[t] = make_uint2(bh, bl);
    }
    for (int t = tid; t < BB * WD; t += MT_TPB) {
        int bb = t / WD, c = t % WD;
        beffs[t] = b_lin_in[c] + g_img_sum[bb][c] / g_img_cnt[bb];
    }
    for (int t = tid; t < DEPTH * WD; t += MT_TPB) bsd[t] = b_mlp[t];
    if (tid < WD) wout_s[tid] = W_out[tid];
    if (tid == 0) bout_s[0] = b_out[0];
    __syncthreads();

    const int n_act = g_nact;
    const int w = tid >> 5;
    const int lane = tid & 31;
    const int g = lane >> 2;
    const int q = lane & 3;
    const int blkbase = blockIdx.x * MT_PTSBLK;

    float wo[8];
#pragma unroll
    for (int nt = 0; nt < 4; nt++) {
        wo[nt * 2 + 0] = wout_s[8 * nt + 2 * q + 0];
        wo[nt * 2 + 1] = wout_s[8 * nt + 2 * q + 1];
    }
    const float boutv = bout_s[0];
    float* mXs = Xs + w * 32 * 9;
    int* myxb = xb + w * 32;
    int* myxp = xp + w * 32;

    if (blkbase < n_act) {
#pragma unroll 1
        for (int it = 0; it < MT_ITERS; it++) {
            if (blkbase + it * MT_ROWS >= n_act) break;
            const int slot = blkbase + it * MT_ROWS + tid;
            const bool valid = slot < n_act;
            const int p = valid ? g_idx[slot] : 0;

            __syncwarp();
            // stage this thread's input row (plain floats, stride 9)
            {
                const float* mp = metadata + (size_t)p * CMETA;
                float* xr = mXs + lane * 9;
#pragma unroll
                for (int i = 0; i < CMETA; i++) xr[i] = mp[i];
                xr[6] = 0.0f; xr[7] = 0.0f;
                myxb[lane] = p / JK;
                myxp[lane] = valid ? p : -1;
            }
            __syncwarp();

            const int b4[4] = { myxb[g], myxb[g + 8], myxb[g + 16], myxb[g + 24] };

            // ---- input layer: A frags from staged rows (cols 2q,2q+1 < 8) ----
            float cc[2][4][4];
#pragma unroll
            for (int mt = 0; mt < 2; mt++)
#pragma unroll
                for (int nt = 0; nt < 4; nt++)
#pragma unroll
                    for (int r = 0; r < 4; r++) cc[mt][nt][r] = 0.0f;

            uint32_t aH[2][2][4], aL[2][2][4];   // [mt][kt][reg] — hidden-layer A frags
            {
                uint32_t iH[2][2], iL[2][2];
#pragma unroll
                for (int mt = 0; mt < 2; mt++) {
                    const int R = 16 * mt;
                    split_h2(mXs[(R + g) * 9 + 2 * q],     mXs[(R + g) * 9 + 2 * q + 1],
                             iH[mt][0], iL[mt][0]);
                    split_h2(mXs[(R + g + 8) * 9 + 2 * q], mXs[(R + g + 8) * 9 + 2 * q + 1],
                             iH[mt][1], iL[mt][1]);
                }
#pragma unroll
                for (int nt = 0; nt < 4; nt++) {
                    uint2 wv = WF0[nt * 32 + lane];
#pragma unroll
                    for (int mt = 0; mt < 2; mt++) {
                        mma_f16(cc[mt][nt], iH[mt][0], iH[mt][1], 0u, 0u, wv.x, 0u);
                        mma_f16(cc[mt][nt], iL[mt][0], iL[mt][1], 0u, 0u, wv.x, 0u);
                        mma_f16(cc[mt][nt], iH[mt][0], iH[mt][1], 0u, 0u, wv.y, 0u);
                    }
                }
            }

            // input epilogue (thread-local): + per-batch bias -> A frags
#pragma unroll
            for (int mt = 0; mt < 2; mt++)
#pragma unroll
                for (int nt = 0; nt < 4; nt++) {
                    const int kt = nt >> 1;
                    const int ai = (nt & 1) * 2;
                    const int c0 = 8 * nt + 2 * q;
                    const float* be0 = &beffs[b4[2 * mt] * WD];
                    const float* be1 = &beffs[b4[2 * mt + 1] * WD];
                    split_h2(cc[mt][nt][0] + be0[c0], cc[mt][nt][1] + be0[c0 + 1],
                             aH[mt][kt][ai], aL[mt][kt][ai]);
                    split_h2(cc[mt][nt][2] + be1[c0], cc[mt][nt][3] + be1[c0 + 1],
                             aH[mt][kt][ai + 1], aL[mt][kt][ai + 1]);
                }

            // ---- hidden layers: activations stay in registers ----
            float acc[4] = {0.0f, 0.0f, 0.0f, 0.0f};
#pragma unroll
            for (int d = 0; d < DEPTH; d++) {
#pragma unroll
                for (int mt = 0; mt < 2; mt++)
#pragma unroll
                    for (int nt = 0; nt < 4; nt++)
#pragma unroll
                        for (int r = 0; r < 4; r++) cc[mt][nt][r] = 0.0f;

#pragma unroll
                for (int kt = 0; kt < 2; kt++) {
#pragma unroll
                    for (int nt = 0; nt < 4; nt++) {
                        uint4 wv = WF4[((d * 2 + kt) * 4 + nt) * 32 + lane];
#pragma unroll
                        for (int mt = 0; mt < 2; mt++) {
                            mma_f16(cc[mt][nt], aH[mt][kt][0], aH[mt][kt][1], aH[mt][kt][2], aH[mt][kt][3], wv.x, wv.y);
                            mma_f16(cc[mt][nt], aL[mt][kt][0], aL[mt][kt][1], aL[mt][kt][2], aL[mt][kt][3], wv.x, wv.y);
                            mma_f16(cc[mt][nt], aH[mt][kt][0], aH[mt][kt][1], aH[mt][kt][2], aH[mt][kt][3], wv.z, wv.w);
                        }
                    }
                }

                if (d < DEPTH - 1) {
                    // thread-local C->A: relu + bias, repack
#pragma unroll
                    for (int mt = 0; mt < 2; mt++)
#pragma unroll
                        for (int nt = 0; nt < 4; nt++) {
                            const int kt = nt >> 1;
                            const int ai = (nt & 1) * 2;
                            const int c0 = 8 * nt + 2 * q;
                            const float bb0 = bsd[d * WD + c0];
                            const float bb1 = bsd[d * WD + c0 + 1];
                            split_h2(fmaxf(cc[mt][nt][0] + bb0, 0.0f),
                                     fmaxf(cc[mt][nt][1] + bb1, 0.0f),
                                     aH[mt][kt][ai], aL[mt][kt][ai]);
                            split_h2(fmaxf(cc[mt][nt][2] + bb0, 0.0f),
                                     fmaxf(cc[mt][nt][3] + bb1, 0.0f),
                                     aH[mt][kt][ai + 1], aL[mt][kt][ai + 1]);
                        }
                } else {
                    // final layer: fold directly into output dot product
#pragma unroll
                    for (int mt = 0; mt < 2; mt++)
#pragma unroll
                        for (int nt = 0; nt < 4; nt++) {
                            const int c0 = 8 * nt + 2 * q;
                            const float bb0 = bsd[d * WD + c0];
                            const float bb1 = bsd[d * WD + c0 + 1];
                            float v0 = fmaxf(cc[mt][nt][0] + bb0, 0.0f);
                            float v1 = fmaxf(cc[mt][nt][1] + bb1, 0.0f);
                            float v2 = fmaxf(cc[mt][nt][2] + bb0, 0.0f);
                            float v3 = fmaxf(cc[mt][nt][3] + bb1, 0.0f);
                            acc[2 * mt]     = fmaf(v0, wo[nt * 2 + 0], fmaf(v1, wo[nt * 2 + 1], acc[2 * mt]));
                            acc[2 * mt + 1] = fmaf(v2, wo[nt * 2 + 0], fmaf(v3, wo[nt * 2 + 1], acc[2 * mt + 1]));
                        }
                }
            }

            // ---- output reduce across the 4-lane column group ----
#pragma unroll
            for (int jj = 0; jj < 4; jj++) {
                acc[jj] += __shfl_xor_sync(0xFFFFFFFFu, acc[jj], 1);
                acc[jj] += __shfl_xor_sync(0xFFFFFFFFu, acc[jj], 2);
            }
            if (q == 0) {
#pragma unroll
                for (int jj = 0; jj < 4; jj++) {
                    int rowl = 16 * (jj >> 1) + g + 8 * (jj & 1);
                    int pt = myxp[rowl];
                    if (pt >= 0) out[pt] = acc[jj] + boutv;
                }
            }
        }
    }

    // replay-state reset: last block out resets everything
    __syncthreads();
    if (tid == 0) {
        int old = atomicAdd(&g_done, 1);
        if (old == (int)gridDim.x - 1) {
            g_nact = 0;
            float* s = &g_img_sum[0][0];
            for (int t = 0; t < BB * WD; t++) s[t] = 0.0f;
            for (int t = 0; t < BB; t++) g_img_cnt[t] = 0.0f;
            __threadfence();
            g_done = 0;
        }
    }
}

// ---------------------------------------------------------------------------
extern "C" void kernel_launch(void* const* d_in, const int* in_sizes, int n_in,
                              void* d_out, int out_size)
{
    const float* Imodel   = (const float*)d_in[0];
    const float* Iobs     = (const float*)d_in[1];
    const float* metadata = (const float*)d_in[2];
    const void*  mask     = d_in[3];
    const float* W_img_in = (const float*)d_in[5];
    const float* b_img_in = (const float*)d_in[6];
    const float* W_img    = (const float*)d_in[7];
    const float* b_img    = (const float*)d_in[8];
    const float* W_lin_in = (const float*)d_in[9];
    const float* b_lin_in = (const float*)d_in[10];
    const float* W_mlp    = (const float*)d_in[11];
    const float* b_mlp    = (const float*)d_in[12];
    const float* W_out    = (const float*)d_in[13];
    const float* b_out    = (const float*)d_in[14];
    float* out = (float*)d_out;

    static int smem_set = 0;
    if (!smem_set) {
        cudaFuncSetAttribute(k_main, cudaFuncAttributeMaxDynamicSharedMemorySize,
                             SMEM_BYTES);
        smem_set = 1;
    }

    k_front<<<IMGB + NCOMPB, 256>>>(mask, Imodel, Iobs, metadata,
                                    W_img_in, b_img_in, W_img, b_img, out);
    k_main<<<NMAINB, MT_TPB, SMEM_BYTES>>>(metadata, W_lin_in, b_lin_in,
                                           W_mlp, b_mlp, W_out, b_out, out);
}

// round 16
// speedup vs baseline: 2.0414x; 1.3704x over previous
#include <cuda_runtime.h>
#include <cuda_fp16.h>
#include <math.h>
#include <stdint.h>
#include <string.h>

// Problem constants
#define BB     16
#define JJ     256
#define KK     384
#define CMETA  6
#define CIN    8
#define WD     32
#define DEPTH  3
#define SS     32
#define JK     (JJ*KK)        // 98304
#define NPTS   (BB*JK)        // 1572864

// tensor k_main config
#define MT_TPB   128
#define MT_ROWS  128
#define MT_ITERS 4
#define MT_PTSBLK (MT_ROWS*MT_ITERS)   // 512
#define NMAINB  (NPTS/MT_PTSBLK)       // 3072

// front kernel
#define RPB   4
#define IMGB  (BB*(SS/RPB))      // 128 image blocks (4 rows each)
#define NTILE (RPB*(KK/32))      // 48 point-tiles per image block
#define CB    256
#define CPT   4
#define NCOMPB (NPTS/(CB*CPT))   // 1536

// k_main dynamic SMEM layout
#define WF4_N   (3*2*4*32)       // 768 uint4, [dkt][nt][lane]
#define WF0_N   (4*32)           // 128 uint2, [nt][lane]
#define XS_N    (4*32*9)
#define SMEM_BYTES (WF4_N*16 + WF0_N*8 + XS_N*4 + (BB*WD + DEPTH*WD + WD + 4)*4 + 2*128*4 + 256)

// Scratch (device globals; zero at module load; k_main's last block re-zeros)
__device__ float g_img_sum[BB][WD];
__device__ float g_img_cnt[BB];
__device__ int   g_nact;
__device__ int   g_done;
__device__ int   g_idx[NPTS];

__device__ __forceinline__ bool mask_at(const void* m, int fmt, int i) {
    if (fmt == 0) return ((const unsigned char*)m)[i] != 0;
    if (fmt == 1) return ((const int*)m)[i] != 0;
    return ((const float*)m)[i] != 0.0f;
}

__device__ __forceinline__ int detect_fmt_block(const void* mask) {
    unsigned int v = ((const unsigned int*)mask)[threadIdx.x & 255];
    int all_int = __syncthreads_and(v <= 1u);
    int all_flt = __syncthreads_and(v == 0u || v == 0x3F800000u);
    return all_int ? 1 : (all_flt ? 2 : 0);
}

__device__ __forceinline__ unsigned int rotl32(unsigned int x, int r) {
    return (x << r) | (x >> (32 - r));
}

// ---- fp16 split helpers ----
__device__ __forceinline__ uint32_t h2u(__half2 h) {
    uint32_t u; memcpy(&u, &h, 4); return u;
}
__device__ __forceinline__ void split_h2(float v0, float v1,
                                         uint32_t& hi2, uint32_t& lo2) {
    __half2 h = __floats2half2_rn(v0, v1);
    float e0 = __low2float(h);
    float e1 = __high2float(h);
    __half2 l = __floats2half2_rn(v0 - e0, v1 - e1);
    hi2 = h2u(h); lo2 = h2u(l);
}
__device__ __forceinline__ void mma_f16(float c[4],
                                        uint32_t a0, uint32_t a1, uint32_t a2, uint32_t a3,
                                        uint32_t b0, uint32_t b1) {
    asm("mma.sync.aligned.m16n8k16.row.col.f32.f16.f16.f32 "
        "{%0,%1,%2,%3},{%4,%5,%6,%7},{%8,%9},{%0,%1,%2,%3};"
        : "+f"(c[0]), "+f"(c[1]), "+f"(c[2]), "+f"(c[3])
        : "r"(a0), "r"(a1), "r"(a2), "r"(a3), "r"(b0), "r"(b1));
}

// ---------------------------------------------------------------------------
// Front kernel: blocks [0,IMGB) = TENSOR-CORE image branch with local gumbel
// selection (4 rows/block, 8 warps x 6 tiles); blocks [IMGB,..) = compaction.
// ---------------------------------------------------------------------------
__global__ void __launch_bounds__(256) k_front(
    const void* __restrict__ mask,
    const float* __restrict__ Imodel, const float* __restrict__ Iobs,
    const float* __restrict__ metadata,
    const float* __restrict__ W_img_in, const float* __restrict__ b_img_in,
    const float* __restrict__ W_img, const float* __restrict__ b_img,
    float* __restrict__ out)
{
    __shared__ unsigned int keys[JJ];
    __shared__ int selrows[RPB];
    __shared__ __align__(16) uint4 WF4i[WF4_N];
    __shared__ __align__(16) uint2 WF0i[WF0_N];
    __shared__ float bs0[WD];
    __shared__ float bsdi[DEPTH][WD];
    __shared__ __align__(16) float Xs[8][32][9];
    __shared__ float Mk[8][32];
    __shared__ int wsum[8];
    __shared__ int bbase;

    const int fmt = detect_fmt_block(mask);
    const int tid = threadIdx.x;

    if (blockIdx.x >= IMGB) {
        // ---------------- compaction role ----------------
        const int cb = blockIdx.x - IMGB;
        const int lane = tid & 31;
        const int wid = tid >> 5;
        const unsigned int lt = (1u << lane) - 1u;
        const int base = cb * CB * CPT;

        bool act[CPT];
        unsigned int bal[CPT];
        int wcnt = 0;
#pragma unroll
        for (int r = 0; r < CPT; r++) {
            const int p = base + r * CB + tid;
            act[r] = mask_at(mask, fmt, p);
            bal[r] = __ballot_sync(0xFFFFFFFFu, act[r]);
            wcnt += __popc(bal[r]);
            if (!act[r]) out[p] = 0.0f;
        }

        if (lane == 0) wsum[wid] = wcnt;
        __syncthreads();
        if (tid == 0) {
            int tot = 0;
#pragma unroll
            for (int w = 0; w < 8; w++) { int c = wsum[w]; wsum[w] = tot; tot += c; }
            bbase = atomicAdd(&g_nact, tot);
        }
        __syncthreads();

        int off = bbase + wsum[wid];
#pragma unroll
        for (int r = 0; r < CPT; r++) {
            if (act[r]) g_idx[off + __popc(bal[r] & lt)] = base + r * CB + tid;
            off += __popc(bal[r]);
        }
        return;
    }

    // ---------------- image role ----------------
    const int b = blockIdx.x / (SS / RPB);
    const int s0 = (blockIdx.x % (SS / RPB)) * RPB;

    // --- local gumbel selection (row j = tid) ---
    {
        const int j = tid;
        const int rbase = (b * JJ + j) * KK;
        bool alive = false;
        for (int k = 0; k < KK; k++) {
            if (mask_at(mask, fmt, rbase + k)) { alive = true; break; }
        }

        const unsigned int n = (unsigned int)(b * JJ + j);
        unsigned int x0 = 0u;
        unsigned int x1 = n;
        const unsigned int ks0 = 0u;
        const unsigned int ks1 = 42u;
        const unsigned int ks2 = 0x1BD11BDAu ^ 42u;
        x0 += ks0; x1 += ks1;
#define TF_ROUND(r) { x0 += x1; x1 = rotl32(x1, (r)); x1 ^= x0; }
        TF_ROUND(13) TF_ROUND(15) TF_ROUND(26) TF_ROUND(6)
        x0 += ks1; x1 += ks2 + 1u;
        TF_ROUND(17) TF_ROUND(29) TF_ROUND(16) TF_ROUND(24)
        x0 += ks2; x1 += ks0 + 2u;
        TF_ROUND(13) TF_ROUND(15) TF_ROUND(26) TF_ROUND(6)
        x0 += ks0; x1 += ks1 + 3u;
        TF_ROUND(17) TF_ROUND(29) TF_ROUND(16) TF_ROUND(24)
        x0 += ks1; x1 += ks2 + 4u;
        TF_ROUND(13) TF_ROUND(15) TF_ROUND(26) TF_ROUND(6)
        x0 += ks2; x1 += ks0 + 5u;
#undef TF_ROUND
        const unsigned int bits = x0 ^ x1;
        const unsigned int keyv = alive ? ((bits >> 9) | 0x80000000u) : 0u;
        keys[j] = keyv;
        __syncthreads();

        int rank = 0;
        for (int t = 0; t < JJ; t++) {
            unsigned int s = keys[t];
            if (s > keyv || (s == keyv && t < j)) rank++;
        }
        if (rank >= s0 && rank < s0 + RPB) selrows[rank - s0] = j;
    }

    // --- stage weight fragments (image weights) ---
    for (int t = tid; t < WF4_N; t += 256) {
        int lane = t & 31, nt = (t >> 5) & 3, dkt = t >> 7;
        int d = dkt >> 1, kt = dkt & 1;
        int n = (lane >> 2) + 8 * nt;
        int k0 = 2 * (lane & 3) + 16 * kt;
        uint32_t b0h, b0l, b1h, b1l;
        split_h2(W_img[(d * WD + k0) * WD + n],     W_img[(d * WD + k0 + 1) * WD + n], b0h, b0l);
        split_h2(W_img[(d * WD + k0 + 8) * WD + n], W_img[(d * WD + k0 + 9) * WD + n], b1h, b1l);
        WF4i[t] = make_uint4(b0h, b1h, b0l, b1l);
    }
    for (int t = tid; t < WF0_N; t += 256) {
        int lane = t & 31, nt = t >> 5;
        int n = (lane >> 2) + 8 * nt;
        int k0 = 2 * (lane & 3);          // k0, k0+1 < 8 always (CIN=8)
        uint32_t bh, bl;
        split_h2(W_img_in[k0 * WD + n], W_img_in[(k0 + 1) * WD + n], bh, bl);
        WF0i[t] = make_uint2(bh, bl);
    }
    for (int t = tid; t < WD; t += 256) bs0[t] = b_img_in[t];
    for (int t = tid; t < DEPTH * WD; t += 256) bsdi[t / WD][t % WD] = b_img[t];
    __syncthreads();

    const int w = tid >> 5;
    const int lane = tid & 31;
    const int g = lane >> 2;
    const int q = lane & 3;
    float* mXs = &Xs[w][0][0];
    float* mMk = &Mk[w][0];

    float colacc[8];
#pragma unroll
    for (int k = 0; k < 8; k++) colacc[k] = 0.0f;
    float cntacc = 0.0f;

#pragma unroll 1
    for (int t = w; t < NTILE; t += 8) {
        const int rr = t / (KK / 32);
        const int kk0 = (t % (KK / 32)) * 32;
        const int j = selrows[rr];
        const int p = (b * JJ + j) * KK + kk0 + lane;

        __syncwarp();
        // stage point: x = [Imodel, Iobs, md0..5], mask
        {
            float* xr = mXs + lane * 9;
            xr[0] = Imodel[p];
            xr[1] = Iobs[p];
            const float* mp = metadata + (size_t)p * CMETA;
#pragma unroll
            for (int i = 0; i < CMETA; i++) xr[2 + i] = mp[i];
            mMk[lane] = mask_at(mask, fmt, p) ? 1.0f : 0.0f;
        }
        __syncwarp();
        cntacc += mMk[lane];

        // ---- input layer ----
        float cc[2][4][4];
#pragma unroll
        for (int mt = 0; mt < 2; mt++)
#pragma unroll
            for (int nt = 0; nt < 4; nt++)
#pragma unroll
                for (int r = 0; r < 4; r++) cc[mt][nt][r] = 0.0f;

        uint32_t aH[2][2][4], aL[2][2][4];
        {
            uint32_t iH[2][2], iL[2][2];
#pragma unroll
            for (int mt = 0; mt < 2; mt++) {
                const int R = 16 * mt;
                split_h2(mXs[(R + g) * 9 + 2 * q],     mXs[(R + g) * 9 + 2 * q + 1],
                         iH[mt][0], iL[mt][0]);
                split_h2(mXs[(R + g + 8) * 9 + 2 * q], mXs[(R + g + 8) * 9 + 2 * q + 1],
                         iH[mt][1], iL[mt][1]);
            }
#pragma unroll
            for (int nt = 0; nt < 4; nt++) {
                uint2 wv = WF0i[nt * 32 + lane];
#pragma unroll
                for (int mt = 0; mt < 2; mt++) {
                    mma_f16(cc[mt][nt], iH[mt][0], iH[mt][1], 0u, 0u, wv.x, 0u);
                    mma_f16(cc[mt][nt], iL[mt][0], iL[mt][1], 0u, 0u, wv.x, 0u);
                    mma_f16(cc[mt][nt], iH[mt][0], iH[mt][1], 0u, 0u, wv.y, 0u);
                }
            }
        }

        // input epilogue: + bias (no relu) -> A frags
#pragma unroll
        for (int mt = 0; mt < 2; mt++)
#pragma unroll
            for (int nt = 0; nt < 4; nt++) {
                const int kt = nt >> 1;
                const int ai = (nt & 1) * 2;
                const int c0 = 8 * nt + 2 * q;
                split_h2(cc[mt][nt][0] + bs0[c0], cc[mt][nt][1] + bs0[c0 + 1],
                         aH[mt][kt][ai], aL[mt][kt][ai]);
                split_h2(cc[mt][nt][2] + bs0[c0], cc[mt][nt][3] + bs0[c0 + 1],
                         aH[mt][kt][ai + 1], aL[mt][kt][ai + 1]);
            }

        // ---- hidden layers ----
#pragma unroll
        for (int d = 0; d < DEPTH; d++) {
#pragma unroll
            for (int mt = 0; mt < 2; mt++)
#pragma unroll
                for (int nt = 0; nt < 4; nt++)
#pragma unroll
                    for (int r = 0; r < 4; r++) cc[mt][nt][r] = 0.0f;

#pragma unroll
            for (int kt = 0; kt < 2; kt++) {
#pragma unroll
                for (int nt = 0; nt < 4; nt++) {
                    uint4 wv = WF4i[((d * 2 + kt) * 4 + nt) * 32 + lane];
#pragma unroll
                    for (int mt = 0; mt < 2; mt++) {
                        mma_f16(cc[mt][nt], aH[mt][kt][0], aH[mt][kt][1], aH[mt][kt][2], aH[mt][kt][3], wv.x, wv.y);
                        mma_f16(cc[mt][nt], aL[mt][kt][0], aL[mt][kt][1], aL[mt][kt][2], aL[mt][kt][3], wv.x, wv.y);
                        mma_f16(cc[mt][nt], aH[mt][kt][0], aH[mt][kt][1], aH[mt][kt][2], aH[mt][kt][3], wv.z, wv.w);
                    }
                }
            }

            if (d < DEPTH - 1) {
#pragma unroll
                for (int mt = 0; mt < 2; mt++)
#pragma unroll
                    for (int nt = 0; nt < 4; nt++) {
                        const int kt = nt >> 1;
                        const int ai = (nt & 1) * 2;
                        const int c0 = 8 * nt + 2 * q;
                        const float bb0 = bsdi[d][c0];
                        const float bb1 = bsdi[d][c0 + 1];
                        split_h2(fmaxf(cc[mt][nt][0] + bb0, 0.0f),
                                 fmaxf(cc[mt][nt][1] + bb1, 0.0f),
                                 aH[mt][kt][ai], aL[mt][kt][ai]);
                        split_h2(fmaxf(cc[mt][nt][2] + bb0, 0.0f),
                                 fmaxf(cc[mt][nt][3] + bb1, 0.0f),
                                 aH[mt][kt][ai + 1], aL[mt][kt][ai + 1]);
                    }
            } else {
                // final layer: masked column accumulation
#pragma unroll
                for (int mt = 0; mt < 2; mt++) {
                    const float m0 = mMk[16 * mt + g];
                    const float m1 = mMk[16 * mt + g + 8];
#pragma unroll
                    for (int nt = 0; nt < 4; nt++) {
                        const int c0 = 8 * nt + 2 * q;
                        const float bb0 = bsdi[d][c0];
                        const float bb1 = bsdi[d][c0 + 1];
                        float v0 = fmaxf(cc[mt][nt][0] + bb0, 0.0f);
                        float v1 = fmaxf(cc[mt][nt][1] + bb1, 0.0f);
                        float v2 = fmaxf(cc[mt][nt][2] + bb0, 0.0f);
                        float v3 = fmaxf(cc[mt][nt][3] + bb1, 0.0f);
                        colacc[nt * 2 + 0] += m0 * v0 + m1 * v2;
                        colacc[nt * 2 + 1] += m0 * v1 + m1 * v3;
                    }
                }
            }
        }
    }

    // reduce colacc over g-lanes (xor 4,8,16), then q-lane flushes 8 columns
#pragma unroll
    for (int k = 0; k < 8; k++) {
        colacc[k] += __shfl_xor_sync(0xFFFFFFFFu, colacc[k], 4);
        colacc[k] += __shfl_xor_sync(0xFFFFFFFFu, colacc[k], 8);
        colacc[k] += __shfl_xor_sync(0xFFFFFFFFu, colacc[k], 16);
    }
    if (lane < 4) {
#pragma unroll
        for (int nt = 0; nt < 4; nt++) {
            atomicAdd(&g_img_sum[b][8 * nt + 2 * lane + 0], colacc[nt * 2 + 0]);
            atomicAdd(&g_img_sum[b][8 * nt + 2 * lane + 1], colacc[nt * 2 + 1]);
        }
    }
#pragma unroll
    for (int o = 16; o > 0; o >>= 1) cntacc += __shfl_xor_sync(0xFFFFFFFFu, cntacc, o);
    if (lane == 0) atomicAdd(&g_img_cnt[b], cntacc);
}

// ---------------------------------------------------------------------------
// Kernel 2: fp16 Markidis tensor k_main, register-resident activations.
// ---------------------------------------------------------------------------
__global__ void __launch_bounds__(MT_TPB, 4) k_main(
    const float* __restrict__ metadata,
    const float* __restrict__ W_lin_in, const float* __restrict__ b_lin_in,
    const float* __restrict__ W_mlp, const float* __restrict__ b_mlp,
    const float* __restrict__ W_out, const float* __restrict__ b_out,
    float* __restrict__ out)
{
    extern __shared__ __align__(16) unsigned char dynsmem[];
    uint4* WF4   = (uint4*)dynsmem;
    uint2* WF0   = (uint2*)(WF4 + WF4_N);
    float* Xs    = (float*)(WF0 + WF0_N);
    float* beffs = Xs + XS_N;
    float* bsd   = beffs + BB * WD;
    float* wout_s= bsd + DEPTH * WD;
    float* bout_s= wout_s + WD;
    int*   xb    = (int*)(bout_s + 4);
    int*   xp    = xb + 128;

    const int tid = threadIdx.x;

    for (int t = tid; t < WF4_N; t += MT_TPB) {
        int lane = t & 31, nt = (t >> 5) & 3, dkt = t >> 7;
        int d = dkt >> 1, kt = dkt & 1;
        int n = (lane >> 2) + 8 * nt;
        int k0 = 2 * (lane & 3) + 16 * kt;
        uint32_t b0h, b0l, b1h, b1l;
        split_h2(W_mlp[(d * WD + k0) * WD + n],     W_mlp[(d * WD + k0 + 1) * WD + n], b0h, b0l);
        split_h2(W_mlp[(d * WD + k0 + 8) * WD + n], W_mlp[(d * WD + k0 + 9) * WD + n], b1h, b1l);
        WF4[t] = make_uint4(b0h, b1h, b0l, b1l);
    }
    for (int t = tid; t < WF0_N; t += MT_TPB) {
        int lane = t & 31, nt = t >> 5;
        int n = (lane >> 2) + 8 * nt;
        int k0 = 2 * (lane & 3);
        float w0 = (k0 < CMETA) ? W_lin_in[k0 * WD + n] : 0.0f;
        float w1 = (k0 + 1 < CMETA) ? W_lin_in[(k0 + 1) * WD + n] : 0.0f;
        uint32_t bh, bl;
        split_h2(w0, w1, bh, bl);
        WF0[t] = make_uint2(bh, bl);
    }
    for (int t = tid; t < BB * WD; t += MT_TPB) {
        int bb = t / WD, c = t % WD;
        beffs[t] = b_lin_in[c] + g_img_sum[bb][c] / g_img_cnt[bb];
    }
    for (int t = tid; t < DEPTH * WD; t += MT_TPB) bsd[t] = b_mlp[t];
    if (tid < WD) wout_s[tid] = W_out[tid];
    if (tid == 0) bout_s[0] = b_out[0];
    __syncthreads();

    const int n_act = g_nact;
    const int w = tid >> 5;
    const int lane = tid & 31;
    const int g = lane >> 2;
    const int q = lane & 3;
    const int blkbase = blockIdx.x * MT_PTSBLK;

    float wo[8];
#pragma unroll
    for (int nt = 0; nt < 4; nt++) {
        wo[nt * 2 + 0] = wout_s[8 * nt + 2 * q + 0];
        wo[nt * 2 + 1] = wout_s[8 * nt + 2 * q + 1];
    }
    const float boutv = bout_s[0];
    float* mXs = Xs + w * 32 * 9;
    int* myxb = xb + w * 32;
    int* myxp = xp + w * 32;

    if (blkbase < n_act) {
#pragma unroll 1
        for (int it = 0; it < MT_ITERS; it++) {
            if (blkbase + it * MT_ROWS >= n_act) break;
            const int slot = blkbase + it * MT_ROWS + tid;
            const bool valid = slot < n_act;
            const int p = valid ? g_idx[slot] : 0;

            __syncwarp();
            {
                const float* mp = metadata + (size_t)p * CMETA;
                float* xr = mXs + lane * 9;
#pragma unroll
                for (int i = 0; i < CMETA; i++) xr[i] = mp[i];
                xr[6] = 0.0f; xr[7] = 0.0f;
                myxb[lane] = p / JK;
                myxp[lane] = valid ? p : -1;
            }
            __syncwarp();

            const int b4[4] = { myxb[g], myxb[g + 8], myxb[g + 16], myxb[g + 24] };

            float cc[2][4][4];
#pragma unroll
            for (int mt = 0; mt < 2; mt++)
#pragma unroll
                for (int nt = 0; nt < 4; nt++)
#pragma unroll
                    for (int r = 0; r < 4; r++) cc[mt][nt][r] = 0.0f;

            uint32_t aH[2][2][4], aL[2][2][4];
            {
                uint32_t iH[2][2], iL[2][2];
#pragma unroll
                for (int mt = 0; mt < 2; mt++) {
                    const int R = 16 * mt;
                    split_h2(mXs[(R + g) * 9 + 2 * q],     mXs[(R + g) * 9 + 2 * q + 1],
                             iH[mt][0], iL[mt][0]);
                    split_h2(mXs[(R + g + 8) * 9 + 2 * q], mXs[(R + g + 8) * 9 + 2 * q + 1],
                             iH[mt][1], iL[mt][1]);
                }
#pragma unroll
                for (int nt = 0; nt < 4; nt++) {
                    uint2 wv = WF0[nt * 32 + lane];
#pragma unroll
                    for (int mt = 0; mt < 2; mt++) {
                        mma_f16(cc[mt][nt], iH[mt][0], iH[mt][1], 0u, 0u, wv.x, 0u);
                        mma_f16(cc[mt][nt], iL[mt][0], iL[mt][1], 0u, 0u, wv.x, 0u);
                        mma_f16(cc[mt][nt], iH[mt][0], iH[mt][1], 0u, 0u, wv.y, 0u);
                    }
                }
            }

#pragma unroll
            for (int mt = 0; mt < 2; mt++)
#pragma unroll
                for (int nt = 0; nt < 4; nt++) {
                    const int kt = nt >> 1;
                    const int ai = (nt & 1) * 2;
                    const int c0 = 8 * nt + 2 * q;
                    const float* be0 = &beffs[b4[2 * mt] * WD];
                    const float* be1 = &beffs[b4[2 * mt + 1] * WD];
                    split_h2(cc[mt][nt][0] + be0[c0], cc[mt][nt][1] + be0[c0 + 1],
                             aH[mt][kt][ai], aL[mt][kt][ai]);
                    split_h2(cc[mt][nt][2] + be1[c0], cc[mt][nt][3] + be1[c0 + 1],
                             aH[mt][kt][ai + 1], aL[mt][kt][ai + 1]);
                }

            float acc[4] = {0.0f, 0.0f, 0.0f, 0.0f};
#pragma unroll
            for (int d = 0; d < DEPTH; d++) {
#pragma unroll
                for (int mt = 0; mt < 2; mt++)
#pragma unroll
                    for (int nt = 0; nt < 4; nt++)
#pragma unroll
                        for (int r = 0; r < 4; r++) cc[mt][nt][r] = 0.0f;

#pragma unroll
                for (int kt = 0; kt < 2; kt++) {
#pragma unroll
                    for (int nt = 0; nt < 4; nt++) {
                        uint4 wv = WF4[((d * 2 + kt) * 4 + nt) * 32 + lane];
#pragma unroll
                        for (int mt = 0; mt < 2; mt++) {
                            mma_f16(cc[mt][nt], aH[mt][kt][0], aH[mt][kt][1], aH[mt][kt][2], aH[mt][kt][3], wv.x, wv.y);
                            mma_f16(cc[mt][nt], aL[mt][kt][0], aL[mt][kt][1], aL[mt][kt][2], aL[mt][kt][3], wv.x, wv.y);
                            mma_f16(cc[mt][nt], aH[mt][kt][0], aH[mt][kt][1], aH[mt][kt][2], aH[mt][kt][3], wv.z, wv.w);
                        }
                    }
                }

                if (d < DEPTH - 1) {
#pragma unroll
                    for (int mt = 0; mt < 2; mt++)
#pragma unroll
                        for (int nt = 0; nt < 4; nt++) {
                            const int kt = nt >> 1;
                            const int ai = (nt & 1) * 2;
                            const int c0 = 8 * nt + 2 * q;
                            const float bb0 = bsd[d * WD + c0];
                            const float bb1 = bsd[d * WD + c0 + 1];
                            split_h2(fmaxf(cc[mt][nt][0] + bb0, 0.0f),
                                     fmaxf(cc[mt][nt][1] + bb1, 0.0f),
                                     aH[mt][kt][ai], aL[mt][kt][ai]);
                            split_h2(fmaxf(cc[mt][nt][2] + bb0, 0.0f),
                                     fmaxf(cc[mt][nt][3] + bb1, 0.0f),
                                     aH[mt][kt][ai + 1], aL[mt][kt][ai + 1]);
                        }
                } else {
#pragma unroll
                    for (int mt = 0; mt < 2; mt++)
#pragma unroll
                        for (int nt = 0; nt < 4; nt++) {
                            const int c0 = 8 * nt + 2 * q;
                            const float bb0 = bsd[d * WD + c0];
                            const float bb1 = bsd[d * WD + c0 + 1];
                            float v0 = fmaxf(cc[mt][nt][0] + bb0, 0.0f);
                            float v1 = fmaxf(cc[mt][nt][1] + bb1, 0.0f);
                            float v2 = fmaxf(cc[mt][nt][2] + bb0, 0.0f);
                            float v3 = fmaxf(cc[mt][nt][3] + bb1, 0.0f);
                            acc[2 * mt]     = fmaf(v0, wo[nt * 2 + 0], fmaf(v1, wo[nt * 2 + 1], acc[2 * mt]));
                            acc[2 * mt + 1] = fmaf(v2, wo[nt * 2 + 0], fmaf(v3, wo[nt * 2 + 1], acc[2 * mt + 1]));
                        }
                }
            }

#pragma unroll
            for (int jj = 0; jj < 4; jj++) {
                acc[jj] += __shfl_xor_sync(0xFFFFFFFFu, acc[jj], 1);
                acc[jj] += __shfl_xor_sync(0xFFFFFFFFu, acc[jj], 2);
            }
            if (q == 0) {
#pragma unroll
                for (int jj = 0; jj < 4; jj++) {
                    int rowl = 16 * (jj >> 1) + g + 8 * (jj & 1);
                    int pt = myxp[rowl];
                    if (pt >= 0) out[pt] = acc[jj] + boutv;
                }
            }
        }
    }

    __syncthreads();
    if (tid == 0) {
        int old = atomicAdd(&g_done, 1);
        if (old == (int)gridDim.x - 1) {
            g_nact = 0;
            float* s = &g_img_sum[0][0];
            for (int t = 0; t < BB * WD; t++) s[t] = 0.0f;
            for (int t = 0; t < BB; t++) g_img_cnt[t] = 0.0f;
            __threadfence();
            g_done = 0;
        }
    }
}

// ---------------------------------------------------------------------------
extern "C" void kernel_launch(void* const* d_in, const int* in_sizes, int n_in,
                              void* d_out, int out_size)
{
    const float* Imodel   = (const float*)d_in[0];
    const float* Iobs     = (const float*)d_in[1];
    const float* metadata = (const float*)d_in[2];
    const void*  mask     = d_in[3];
    const float* W_img_in = (const float*)d_in[5];
    const float* b_img_in = (const float*)d_in[6];
    const float* W_img    = (const float*)d_in[7];
    const float* b_img    = (const float*)d_in[8];
    const float* W_lin_in = (const float*)d_in[9];
    const float* b_lin_in = (const float*)d_in[10];
    const float* W_mlp    = (const float*)d_in[11];
    const float* b_mlp    = (const float*)d_in[12];
    const float* W_out    = (const float*)d_in[13];
    const float* b_out    = (const float*)d_in[14];
    float* out = (float*)d_out;

    static int smem_set = 0;
    if (!smem_set) {
        cudaFuncSetAttribute(k_main, cudaFuncAttributeMaxDynamicSharedMemorySize,
                             SMEM_BYTES);
        smem_set = 1;
    }

    k_front<<<IMGB + NCOMPB, 256>>>(mask, Imodel, Iobs, metadata,
                                    W_img_in, b_img_in, W_img, b_img, out);
    k_main<<<NMAINB, MT_TPB, SMEM_BYTES>>>(metadata, W_lin_in, b_lin_in,
                                           W_mlp, b_mlp, W_out, b_out, out);
}